// round 9
// baseline (speedup 1.0000x reference)
#include <cuda_runtime.h>
#include <math.h>

#define HID    256
#define CIN    128
#define COUT   128
#define BATCH  32
#define SEQ    4096
#define NROWS  (BATCH*SEQ)
#define CHUNKS 4
#define CHUNK_LEN (SEQ/CHUNKS)
#define WARM   512
#define ASPITCH 100
#define PITERS 120

// ---------------- device scratch (static globals; no runtime allocs) --------
__device__ float g_BA[HID*HID];
__device__ float g_BB[HID*HID];
__device__ float g_scale;
__device__ float g_AT [HID*HID];         // A_norm transposed: AT[k*HID+i] = A[i][k]*s
__device__ float g_WBT[CIN*HID];         // WBT[c*HID+h] = W_B[h][c]
__device__ float g_WCT[HID*COUT];        // WCT[h*COUT+o] = W_C[o][h]
__device__ float g_u [(size_t)NROWS*HID];
__device__ float g_hs[(size_t)NROWS*HID];

// ---------------- 1) B = A^T A ----------------------------------------------
__global__ void k_ata(const float* __restrict__ A) {
    __shared__ float col[HID];
    int i = blockIdx.x, j = threadIdx.x;
    col[j] = A[j*HID + i];
    __syncthreads();
    float a0=0.f,a1=0.f,a2=0.f,a3=0.f;
    #pragma unroll 16
    for (int k = 0; k < HID; k += 4) {
        a0 = fmaf(col[k+0], A[(k+0)*HID + j], a0);
        a1 = fmaf(col[k+1], A[(k+1)*HID + j], a1);
        a2 = fmaf(col[k+2], A[(k+2)*HID + j], a2);
        a3 = fmaf(col[k+3], A[(k+3)*HID + j], a3);
    }
    g_BA[i*HID + j] = (a0+a1)+(a2+a3);
}

// ---------------- 2) B <- B @ B (ping-pong; 7x => B^128) --------------------
__global__ void k_sq(int srcA) {
    const float* __restrict__ Bin = srcA ? g_BA : g_BB;
    float* __restrict__ Bout      = srcA ? g_BB : g_BA;
    __shared__ float row[HID];
    int i = blockIdx.x, j = threadIdx.x;
    row[j] = Bin[i*HID + j];
    __syncthreads();
    float a0=0.f,a1=0.f,a2=0.f,a3=0.f;
    #pragma unroll 16
    for (int k = 0; k < HID; k += 4) {
        a0 = fmaf(row[k+0], Bin[(k+0)*HID + j], a0);
        a1 = fmaf(row[k+1], Bin[(k+1)*HID + j], a1);
        a2 = fmaf(row[k+2], Bin[(k+2)*HID + j], a2);
        a3 = fmaf(row[k+3], Bin[(k+3)*HID + j], a3);
    }
    Bout[i*HID + j] = (a0+a1)+(a2+a3);
}

// ---------------- 3) power iteration on C = B^128 (in g_BB) -----------------
__device__ float red_sum(float v, float* red, int tid) {
    red[tid] = v; __syncthreads();
    for (int s = 128; s > 0; s >>= 1) { if (tid < s) red[tid] += red[tid+s]; __syncthreads(); }
    float r = red[0]; __syncthreads(); return r;
}
__device__ float red_max(float v, float* red, int tid) {
    red[tid] = v; __syncthreads();
    for (int s = 128; s > 0; s >>= 1) { if (tid < s) red[tid] = fmaxf(red[tid], red[tid+s]); __syncthreads(); }
    float r = red[0]; __syncthreads(); return r;
}
__global__ void k_power() {
    __shared__ float v[HID];
    __shared__ float red[HID];
    int tid = threadIdx.x;
    const float* __restrict__ C = g_BB;   // symmetric
    v[tid] = 1.0f;
    __syncthreads();
    float w = 0.f;
    for (int it = 0; it < PITERS; ++it) {
        float a0=0.f,a1=0.f,a2=0.f,a3=0.f;
        #pragma unroll 8
        for (int k = 0; k < HID; k += 4) {   // w[i] = sum_k C[k][i] v[k] (coalesced)
            a0 = fmaf(C[(k+0)*HID + tid], v[k+0], a0);
            a1 = fmaf(C[(k+1)*HID + tid], v[k+1], a1);
            a2 = fmaf(C[(k+2)*HID + tid], v[k+2], a2);
            a3 = fmaf(C[(k+3)*HID + tid], v[k+3], a3);
        }
        w = (a0+a1)+(a2+a3);
        float m = red_max(fabsf(w), red, tid);       // max-norm: no overflow
        float inv = 1.0f / m;
        v[tid] = w * inv;
        __syncthreads();
    }
    // final matvec + Rayleigh quotient
    {
        float a0=0.f,a1=0.f,a2=0.f,a3=0.f;
        #pragma unroll 8
        for (int k = 0; k < HID; k += 4) {
            a0 = fmaf(C[(k+0)*HID + tid], v[k+0], a0);
            a1 = fmaf(C[(k+1)*HID + tid], v[k+1], a1);
            a2 = fmaf(C[(k+2)*HID + tid], v[k+2], a2);
            a3 = fmaf(C[(k+3)*HID + tid], v[k+3], a3);
        }
        w = (a0+a1)+(a2+a3);
    }
    float num = red_sum(v[tid]*w,      red, tid);
    float den = red_sum(v[tid]*v[tid], red, tid);
    if (tid == 0) {
        double mu = (double)num / (double)den;       // ~ sigma^256
        double sigma = exp(log(mu) / 256.0);
        g_scale = (float)(1.0 / (sigma + 1e-5));
    }
}

// ---------------- 4) build AT (scaled), WBT, WCT ----------------------------
__global__ void k_prep(const float* __restrict__ A,
                       const float* __restrict__ WB,
                       const float* __restrict__ WC) {
    int k = blockIdx.x, t = threadIdx.x;         // grid 256, block 256
    float s = g_scale;
    g_AT[k*HID + t] = A[t*HID + k] * s;
    if (k < CIN)  g_WBT[k*HID + t]  = WB[t*CIN + k];
    if (t < COUT) g_WCT[k*COUT + t] = WC[t*HID + k];
}

// ---------------- 5) u projection: u = x @ W_B^T ----------------------------
// block = 256 threads (j = hidden idx), 32 rows per block
__global__ void __launch_bounds__(256) k_uproj(const float* __restrict__ x) {
    __shared__ float xs[CIN*36];                 // xs[k*36 + r]
    int tid = threadIdx.x;
    size_t row0 = (size_t)blockIdx.x * 32;
    for (int idx = tid; idx < 32*CIN; idx += 256) {
        int k = idx & 127, r = idx >> 7;
        xs[k*36 + r] = x[(row0 + r)*CIN + k];
    }
    __syncthreads();
    int j = tid;
    float acc[32];
    #pragma unroll
    for (int r = 0; r < 32; ++r) acc[r] = 0.f;
    #pragma unroll 2
    for (int k = 0; k < CIN; ++k) {
        float wb = g_WBT[k*HID + j];
        #pragma unroll
        for (int r = 0; r < 32; r += 4) {
            float4 xv = *(const float4*)&xs[k*36 + r];
            acc[r+0] = fmaf(wb, xv.x, acc[r+0]);
            acc[r+1] = fmaf(wb, xv.y, acc[r+1]);
            acc[r+2] = fmaf(wb, xv.z, acc[r+2]);
            acc[r+3] = fmaf(wb, xv.w, acc[r+3]);
        }
    }
    #pragma unroll
    for (int r = 0; r < 32; ++r) g_u[(row0 + r)*HID + j] = acc[r];
}

// ---------------- 6) recurrence: 128 CTAs = (chunk, batch) ------------------
// 512 threads: i = tid&255 (output row), half = tid>>8 (k-half).
// Per (i,half): 80 A-cols in registers, 48 from SMEM (pitch 100).
__global__ void __launch_bounds__(512,1) k_rec() {
    extern __shared__ float sm[];
    float* As   = sm;                      // 256*100
    float* h0   = sm + HID*ASPITCH;        // 256
    float* h1   = h0 + HID;                // 256
    float* psum = h1 + HID;                // 256
    const int tid  = threadIdx.x;
    const int i    = tid & 255;
    const int half = tid >> 8;
    const int kbase = half << 7;
    const int b     = blockIdx.x & 31;
    const int chunk = blockIdx.x >> 5;

    float areg[80];
    #pragma unroll
    for (int j = 0; j < 80; ++j) areg[j] = g_AT[(kbase + j)*HID + i];

    for (int idx = tid; idx < 96*256; idx += 512) {
        int i2 = idx & 255, kk = idx >> 8;                 // kk in [0,96)
        int k = (kk < 48) ? (80 + kk) : (160 + kk);        // half0: 80..127, half1: 208..255
        As[i2*ASPITCH + kk] = g_AT[k*HID + i2];
    }
    if (tid < HID) h0[tid] = 0.f;

    const int t0   = (chunk == 0) ? 0 : chunk*CHUNK_LEN - WARM;
    const int t1   = chunk*CHUNK_LEN;
    const int tend = (chunk + 1)*CHUNK_LEN;
    float unext = 0.f;
    if (!half) unext = g_u[((size_t)b*SEQ + t0)*HID + i];
    __syncthreads();

    float* hc = h0; float* hn = h1;
    const float* arow = As + i*ASPITCH + half*48;
    for (int t = t0; t < tend; ++t) {
        const float* h = hc + kbase;
        float a0=0.f,a1=0.f,a2=0.f,a3=0.f;
        #pragma unroll
        for (int j = 0; j < 80; j += 4) {
            float4 h4 = *(const float4*)(h + j);
            a0 = fmaf(areg[j+0], h4.x, a0);
            a1 = fmaf(areg[j+1], h4.y, a1);
            a2 = fmaf(areg[j+2], h4.z, a2);
            a3 = fmaf(areg[j+3], h4.w, a3);
        }
        #pragma unroll
        for (int j = 0; j < 48; j += 4) {
            float4 h4 = *(const float4*)(h + 80 + j);
            float4 a4 = *(const float4*)(arow + j);
            a0 = fmaf(a4.x, h4.x, a0);
            a1 = fmaf(a4.y, h4.y, a1);
            a2 = fmaf(a4.z, h4.z, a2);
            a3 = fmaf(a4.w, h4.w, a3);
        }
        float acc = (a0+a1)+(a2+a3);
        float ucur = unext;
        if (half) {
            psum[i] = acc;
        } else if (t + 1 < tend) {
            unext = g_u[((size_t)b*SEQ + t + 1)*HID + i];
        }
        __syncthreads();
        if (!half) {
            float hv = fmaxf(acc + psum[i] + ucur, 0.f);
            hn[i] = hv;
            if (t >= t1) g_hs[((size_t)b*SEQ + t)*HID + i] = hv;
        }
        __syncthreads();
        float* tmp = hc; hc = hn; hn = tmp;
    }
}

// ---------------- 7) y projection: y = hs @ W_C^T ---------------------------
// block = 256 threads: j = tid&127 (out col), rg = tid>>7; 32 rows per block
__global__ void __launch_bounds__(256) k_yproj(float* __restrict__ y) {
    __shared__ float hst[HID*36];                // hst[k*36 + r]
    int tid = threadIdx.x;
    size_t row0 = (size_t)blockIdx.x * 32;
    for (int idx = tid; idx < 32*HID; idx += 256) {
        int k = idx & 255, r = idx >> 8;
        hst[k*36 + r] = g_hs[(row0 + r)*HID + k];
    }
    __syncthreads();
    int j = tid & 127, rb = (tid >> 7) * 16;
    float acc[16];
    #pragma unroll
    for (int r = 0; r < 16; ++r) acc[r] = 0.f;
    #pragma unroll 2
    for (int k = 0; k < HID; ++k) {
        float wc = g_WCT[k*COUT + j];
        #pragma unroll
        for (int r = 0; r < 16; r += 4) {
            float4 hv = *(const float4*)&hst[k*36 + rb + r];
            acc[r+0] = fmaf(wc, hv.x, acc[r+0]);
            acc[r+1] = fmaf(wc, hv.y, acc[r+1]);
            acc[r+2] = fmaf(wc, hv.z, acc[r+2]);
            acc[r+3] = fmaf(wc, hv.w, acc[r+3]);
        }
    }
    #pragma unroll
    for (int r = 0; r < 16; ++r) y[(row0 + rb + r)*COUT + j] = acc[r];
}

// ---------------- launch ----------------------------------------------------
extern "C" void kernel_launch(void* const* d_in, const int* in_sizes, int n_in,
                              void* d_out, int out_size) {
    const float* x  = (const float*)d_in[0];
    const float* A  = (const float*)d_in[1];
    const float* WB = (const float*)d_in[2];
    const float* WC = (const float*)d_in[3];
    float* y = (float*)d_out;

    static const int REC_SMEM = (HID*ASPITCH + 3*HID) * 4;  // 105472 B
    cudaFuncSetAttribute(k_rec, cudaFuncAttributeMaxDynamicSharedMemorySize, REC_SMEM);

    k_ata<<<HID, HID>>>(A);
    k_sq<<<HID, HID>>>(1);   // BA -> BB
    k_sq<<<HID, HID>>>(0);   // BB -> BA
    k_sq<<<HID, HID>>>(1);
    k_sq<<<HID, HID>>>(0);
    k_sq<<<HID, HID>>>(1);
    k_sq<<<HID, HID>>>(0);
    k_sq<<<HID, HID>>>(1);   // 7th: BA -> BB  (C = B^128 in g_BB)
    k_power<<<1, HID>>>();
    k_prep<<<HID, HID>>>(A, WB, WC);
    k_uproj<<<NROWS/32, 256>>>(x);
    k_rec<<<CHUNKS*BATCH, 512, REC_SMEM>>>();
    k_yproj<<<NROWS/32, 256>>>(y);
}

// round 11
// speedup vs baseline: 1.3676x; 1.3676x over previous
#include <cuda_runtime.h>
#include <cuda_bf16.h>
#include <math.h>
#include <stdint.h>

#define HID    256
#define CIN    128
#define COUT   128
#define BATCH  32
#define SEQ    4096
#define NROWS  (BATCH*SEQ)
#define CHUNKS 32
#define CHUNK_LEN (SEQ/CHUNKS)   /* 128 */
#define WARM   384
#define PITERS 120
#define NB     8                 /* batches per rec CTA */

/* ---- k_rec SMEM word layout ---- */
#define APAN_W   20                   /* words per m-row in a double-panel  */
#define DPAN_SZ  (HID*APAN_W)         /* 5120 words per 2 k-steps           */
#define A1_WORDS (8*DPAN_SZ)          /* 40960 words = 160KB                */
#define HT_PITCH 132                  /* words per n-row of hT              */
#define HT_MAT   (8*HT_PITCH)         /* 1056 words per matrix (h0 or h1)   */
#define HT_BUF   (2*HT_MAT)           /* 2112 words per buffer              */
#define HT_OFF   A1_WORDS
#define SM_WORDS (A1_WORDS + 2*HT_BUF)
#define REC_SMEM (SM_WORDS*4)         /* 180736 bytes */

// ---------------- device scratch ------------------------------------------
__device__ float g_BA[HID*HID];
__device__ float g_BB[HID*HID];
__device__ float g_scale;
__device__ __align__(16) __nv_bfloat16 g_A0[HID*HID];  // bf16(A_norm), row-major
__device__ __align__(16) __nv_bfloat16 g_A1[HID*HID];  // bf16(A_norm - A0)
__device__ float g_WBT[CIN*HID];
__device__ float g_WCT[HID*COUT];
__device__ float g_u [(size_t)NROWS*HID];   // layout [t][b][h]
__device__ float g_hs[(size_t)NROWS*HID];   // layout [t][b][h]

// ---------------- HMMA helper ---------------------------------------------
__device__ __forceinline__ void mma_bf16(float c[4], const uint32_t a[4],
                                         uint32_t b0, uint32_t b1) {
    asm volatile(
        "mma.sync.aligned.m16n8k16.row.col.f32.bf16.bf16.f32 "
        "{%0,%1,%2,%3}, {%4,%5,%6,%7}, {%8,%9}, {%0,%1,%2,%3};\n"
        : "+f"(c[0]), "+f"(c[1]), "+f"(c[2]), "+f"(c[3])
        : "r"(a[0]), "r"(a[1]), "r"(a[2]), "r"(a[3]), "r"(b0), "r"(b1));
}

// ---------------- 1) B = A^T A --------------------------------------------
__global__ void k_ata(const float* __restrict__ A) {
    __shared__ float col[HID];
    int i = blockIdx.x, j = threadIdx.x;
    col[j] = A[j*HID + i];
    __syncthreads();
    float a0=0.f,a1=0.f,a2=0.f,a3=0.f;
    #pragma unroll 16
    for (int k = 0; k < HID; k += 4) {
        a0 = fmaf(col[k+0], A[(k+0)*HID + j], a0);
        a1 = fmaf(col[k+1], A[(k+1)*HID + j], a1);
        a2 = fmaf(col[k+2], A[(k+2)*HID + j], a2);
        a3 = fmaf(col[k+3], A[(k+3)*HID + j], a3);
    }
    g_BA[i*HID + j] = (a0+a1)+(a2+a3);
}

// ---------------- 2) B <- B@B (7x => B^128) -------------------------------
__global__ void k_sq(int srcA) {
    const float* __restrict__ Bin = srcA ? g_BA : g_BB;
    float* __restrict__ Bout      = srcA ? g_BB : g_BA;
    __shared__ float row[HID];
    int i = blockIdx.x, j = threadIdx.x;
    row[j] = Bin[i*HID + j];
    __syncthreads();
    float a0=0.f,a1=0.f,a2=0.f,a3=0.f;
    #pragma unroll 16
    for (int k = 0; k < HID; k += 4) {
        a0 = fmaf(row[k+0], Bin[(k+0)*HID + j], a0);
        a1 = fmaf(row[k+1], Bin[(k+1)*HID + j], a1);
        a2 = fmaf(row[k+2], Bin[(k+2)*HID + j], a2);
        a3 = fmaf(row[k+3], Bin[(k+3)*HID + j], a3);
    }
    Bout[i*HID + j] = (a0+a1)+(a2+a3);
}

// ---------------- 3) power iteration on C = B^128 -------------------------
__device__ float red_sum(float v, float* red, int tid) {
    red[tid] = v; __syncthreads();
    for (int s = 128; s > 0; s >>= 1) { if (tid < s) red[tid] += red[tid+s]; __syncthreads(); }
    float r = red[0]; __syncthreads(); return r;
}
__device__ float red_max(float v, float* red, int tid) {
    red[tid] = v; __syncthreads();
    for (int s = 128; s > 0; s >>= 1) { if (tid < s) red[tid] = fmaxf(red[tid], red[tid+s]); __syncthreads(); }
    float r = red[0]; __syncthreads(); return r;
}
__global__ void k_power() {
    __shared__ float v[HID];
    __shared__ float red[HID];
    int tid = threadIdx.x;
    const float* __restrict__ C = g_BB;
    v[tid] = 1.0f;
    __syncthreads();
    float w = 0.f;
    for (int it = 0; it < PITERS; ++it) {
        float a0=0.f,a1=0.f,a2=0.f,a3=0.f;
        #pragma unroll 8
        for (int k = 0; k < HID; k += 4) {
            a0 = fmaf(C[(k+0)*HID + tid], v[k+0], a0);
            a1 = fmaf(C[(k+1)*HID + tid], v[k+1], a1);
            a2 = fmaf(C[(k+2)*HID + tid], v[k+2], a2);
            a3 = fmaf(C[(k+3)*HID + tid], v[k+3], a3);
        }
        w = (a0+a1)+(a2+a3);
        float m = red_max(fabsf(w), red, tid);
        v[tid] = w * (1.0f/m);
        __syncthreads();
    }
    {
        float a0=0.f,a1=0.f,a2=0.f,a3=0.f;
        #pragma unroll 8
        for (int k = 0; k < HID; k += 4) {
            a0 = fmaf(C[(k+0)*HID + tid], v[k+0], a0);
            a1 = fmaf(C[(k+1)*HID + tid], v[k+1], a1);
            a2 = fmaf(C[(k+2)*HID + tid], v[k+2], a2);
            a3 = fmaf(C[(k+3)*HID + tid], v[k+3], a3);
        }
        w = (a0+a1)+(a2+a3);
    }
    float num = red_sum(v[tid]*w,      red, tid);
    float den = red_sum(v[tid]*v[tid], red, tid);
    if (tid == 0) {
        double mu = (double)num / (double)den;       // ~ sigma^256
        double sigma = exp(log(mu) / 256.0);
        g_scale = (float)(1.0 / (sigma + 1e-5));
    }
}

// ---------------- 4) prep: A0/A1 bf16 split, WBT, WCT ---------------------
__global__ void k_prep(const float* __restrict__ A,
                       const float* __restrict__ WB,
                       const float* __restrict__ WC) {
    int bi = blockIdx.x, tj = threadIdx.x;       // 256 x 256
    float s = g_scale;
    float an = A[bi*HID + tj] * s;
    __nv_bfloat16 a0 = __float2bfloat16(an);
    g_A0[bi*HID + tj] = a0;
    g_A1[bi*HID + tj] = __float2bfloat16(an - __bfloat162float(a0));
    if (bi < CIN)  g_WBT[bi*HID + tj]  = WB[tj*CIN + bi];
    if (tj < COUT) g_WCT[bi*COUT + tj] = WC[tj*HID + bi];
}

// ---------------- 5) u = x @ W_B^T  (writes [t][b][h]) --------------------
__global__ void __launch_bounds__(256) k_uproj(const float* __restrict__ x) {
    __shared__ float xs[CIN*36];
    int tid = threadIdx.x;
    size_t row0 = (size_t)blockIdx.x * 32;       // b-major row = b*SEQ + t
    for (int idx = tid; idx < 32*CIN; idx += 256) {
        int k = idx & 127, r = idx >> 7;
        xs[k*36 + r] = x[(row0 + r)*CIN + k];
    }
    __syncthreads();
    int j = tid;
    float acc[32];
    #pragma unroll
    for (int r = 0; r < 32; ++r) acc[r] = 0.f;
    #pragma unroll 2
    for (int k = 0; k < CIN; ++k) {
        float wb = g_WBT[k*HID + j];
        #pragma unroll
        for (int r = 0; r < 32; r += 4) {
            float4 xv = *(const float4*)&xs[k*36 + r];
            acc[r+0] = fmaf(wb, xv.x, acc[r+0]);
            acc[r+1] = fmaf(wb, xv.y, acc[r+1]);
            acc[r+2] = fmaf(wb, xv.z, acc[r+2]);
            acc[r+3] = fmaf(wb, xv.w, acc[r+3]);
        }
    }
    int b = (int)(row0 >> 12);
    int t_base = (int)(row0 & 4095);
    #pragma unroll
    for (int r = 0; r < 32; ++r)
        g_u[((size_t)(t_base + r)*BATCH + b)*HID + j] = acc[r];
}

// ---------------- 6) recurrence on mma.sync bf16 --------------------------
// 128 CTAs = 32 chunks x 4 batch-groups (NB=8). 256 threads = 8 warps.
// Warp w owns m-rows [32w, 32w+32) as two m16 tiles. Full K per warp.
// D = A0.h0 + A0.h1 + A1.h0 ; A0 reg-resident, A1 streamed from SMEM panels.
__global__ void __launch_bounds__(256,1) k_rec() {
    extern __shared__ uint32_t sw[];
    const int tid = threadIdx.x;
    const int w = tid >> 5, l = tid & 31, g = l >> 2, tg = l & 3;
    const int wb = w * 32;
    const int chunk = blockIdx.x >> 2, bbase = (blockIdx.x & 3) * NB;

    // ---- A1 -> SMEM panels (pitch-20 words per m-row, 2 k-steps per row) --
    {
        const uint32_t* A1w = (const uint32_t*)g_A1;     // word = m*128 + k/2
        for (int p = tid; p < HID*HID/2; p += 256) {
            int m = p >> 7, c128 = p & 127;              // c128 = global k-pair
            int ks = c128 >> 3, ci = c128 & 7;
            sw[(ks>>1)*DPAN_SZ + m*APAN_W + (ks&1)*8 + ci] = A1w[p];
        }
    }
    // ---- zero hT (both buffers) => h(t0) = 0 ------------------------------
    for (int p = tid; p < 2*HT_BUF; p += 256) sw[HT_OFF + p] = 0;

    // ---- A0 fragments -> registers ----------------------------------------
    uint32_t a0f[2][16][4];
    {
        const uint32_t* A0w = (const uint32_t*)g_A0;
        #pragma unroll
        for (int mt = 0; mt < 2; ++mt) {
            int mr = wb + mt*16 + g;
            #pragma unroll
            for (int ks = 0; ks < 16; ++ks) {
                int base = 8*ks + tg;
                a0f[mt][ks][0] = A0w[(size_t)mr*128 + base];
                a0f[mt][ks][1] = A0w[(size_t)(mr+8)*128 + base];
                a0f[mt][ks][2] = A0w[(size_t)mr*128 + base + 4];
                a0f[mt][ks][3] = A0w[(size_t)(mr+8)*128 + base + 4];
            }
        }
    }
    __syncthreads();

    int t0 = chunk*CHUNK_LEN - WARM; if (t0 < 0) t0 = 0;
    const int t1 = chunk*CHUNK_LEN, tend = t1 + CHUNK_LEN;

    int par = 0;
    for (int t = t0; t < tend; ++t, par ^= 1) {
        const int rd = par, wr = par ^ 1;

        // prefetch u(t) fragments (layout [t][b][h])
        float ur[2][4];
        {
            const float* ub = g_u + (size_t)((size_t)t*BATCH + bbase)*HID;
            #pragma unroll
            for (int mt = 0; mt < 2; ++mt) {
                int m0 = wb + mt*16 + g;
                ur[mt][0] = ub[(2*tg  )*HID + m0    ];
                ur[mt][1] = ub[(2*tg+1)*HID + m0    ];
                ur[mt][2] = ub[(2*tg  )*HID + m0 + 8];
                ur[mt][3] = ub[(2*tg+1)*HID + m0 + 8];
            }
        }

        float acc[2][4] = {{0.f,0.f,0.f,0.f},{0.f,0.f,0.f,0.f}};
        const uint32_t* hb = sw + HT_OFF + rd*HT_BUF;
        #pragma unroll
        for (int ks = 0; ks < 16; ++ks) {
            int bw = g*HT_PITCH + 8*ks + tg;
            uint32_t b00 = hb[bw],          b01 = hb[bw + 4];
            uint32_t b10 = hb[HT_MAT + bw], b11 = hb[HT_MAT + bw + 4];
            const uint32_t* pan = sw + (ks>>1)*DPAN_SZ + (ks&1)*8;
            #pragma unroll
            for (int mt = 0; mt < 2; ++mt) {
                int mr = wb + mt*16 + g;
                uint32_t a1f[4];
                a1f[0] = pan[mr*APAN_W + tg];
                a1f[1] = pan[(mr+8)*APAN_W + tg];
                a1f[2] = pan[mr*APAN_W + tg + 4];
                a1f[3] = pan[(mr+8)*APAN_W + tg + 4];
                mma_bf16(acc[mt], a0f[mt][ks], b00, b01);   // A0 . h0
                mma_bf16(acc[mt], a0f[mt][ks], b10, b11);   // A0 . h1
                mma_bf16(acc[mt], a1f,         b00, b01);   // A1 . h0
            }
        }

        // epilogue: relu(acc+u) -> split bf16 -> hT[wr]; optional hs store
        {
            uint32_t wbw = HT_OFF + wr*HT_BUF;
            float* hsb = g_hs + (size_t)((size_t)t*BATCH + bbase)*HID;
            bool emit = (t >= t1);
            #pragma unroll
            for (int mt = 0; mt < 2; ++mt) {
                int m0 = wb + mt*16 + g;
                #pragma unroll
                for (int q = 0; q < 4; ++q) {
                    int m = m0 + ((q >= 2) ? 8 : 0);
                    int n = 2*tg + (q & 1);
                    float hv = fmaxf(acc[mt][q] + ur[mt][q], 0.f);
                    __nv_bfloat16 h0 = __float2bfloat16(hv);
                    __nv_bfloat16 h1 = __float2bfloat16(hv - __bfloat162float(h0));
                    ((uint16_t*)(sw + wbw + n*HT_PITCH))[m]          = __bfloat16_as_ushort(h0);
                    ((uint16_t*)(sw + wbw + HT_MAT + n*HT_PITCH))[m] = __bfloat16_as_ushort(h1);
                    if (emit) hsb[(size_t)n*HID + m] = hv;
                }
            }
        }
        __syncthreads();
    }
}

// ---------------- 7) y = hs @ W_C^T  (reads [t][b][h]) --------------------
__global__ void __launch_bounds__(256) k_yproj(float* __restrict__ y) {
    __shared__ float hst[HID*36];
    int tid = threadIdx.x;
    size_t row0 = (size_t)blockIdx.x * 32;       // row = t*BATCH + b
    for (int idx = tid; idx < 32*HID; idx += 256) {
        int k = idx & 255, r = idx >> 8;
        hst[k*36 + r] = g_hs[(row0 + r)*HID + k];
    }
    __syncthreads();
    int j = tid & 127, rb = (tid >> 7) * 16;
    float acc[16];
    #pragma unroll
    for (int r = 0; r < 16; ++r) acc[r] = 0.f;
    #pragma unroll 2
    for (int k = 0; k < HID; ++k) {
        float wc = g_WCT[k*COUT + j];
        #pragma unroll
        for (int r = 0; r < 16; r += 4) {
            float4 hv = *(const float4*)&hst[k*36 + rb + r];
            acc[r+0] = fmaf(wc, hv.x, acc[r+0]);
            acc[r+1] = fmaf(wc, hv.y, acc[r+1]);
            acc[r+2] = fmaf(wc, hv.z, acc[r+2]);
            acc[r+3] = fmaf(wc, hv.w, acc[r+3]);
        }
    }
    int t = (int)(row0 >> 5);
    #pragma unroll
    for (int r = 0; r < 16; ++r) {
        int b = rb + r;
        y[((size_t)b*SEQ + t)*COUT + j] = acc[r];
    }
}

// ---------------- launch ---------------------------------------------------
extern "C" void kernel_launch(void* const* d_in, const int* in_sizes, int n_in,
                              void* d_out, int out_size) {
    const float* x  = (const float*)d_in[0];
    const float* A  = (const float*)d_in[1];
    const float* WB = (const float*)d_in[2];
    const float* WC = (const float*)d_in[3];
    float* y = (float*)d_out;

    cudaFuncSetAttribute(k_rec, cudaFuncAttributeMaxDynamicSharedMemorySize, REC_SMEM);

    k_ata<<<HID, HID>>>(A);
    k_sq<<<HID, HID>>>(1);
    k_sq<<<HID, HID>>>(0);
    k_sq<<<HID, HID>>>(1);
    k_sq<<<HID, HID>>>(0);
    k_sq<<<HID, HID>>>(1);
    k_sq<<<HID, HID>>>(0);
    k_sq<<<HID, HID>>>(1);            // C = B^128 in g_BB
    k_power<<<1, HID>>>();
    k_prep<<<HID, HID>>>(A, WB, WC);
    k_uproj<<<NROWS/32, 256>>>(x);
    k_rec<<<CHUNKS*(BATCH/NB), 256, REC_SMEM>>>();
    k_yproj<<<NROWS/32, 256>>>(y);
}

// round 12
// speedup vs baseline: 1.7009x; 1.2437x over previous
#include <cuda_runtime.h>
#include <cuda_bf16.h>
#include <math.h>
#include <stdint.h>

#define HID    256
#define CIN    128
#define COUT   128
#define BATCH  32
#define SEQ    4096
#define NROWS  (BATCH*SEQ)
#define CHUNKS 32
#define CHUNK_LEN (SEQ/CHUNKS)   /* 128 */
#define WARM   384
#define PITERS 32
#define NB     8                 /* batches per rec CTA */

/* ---- k_rec SMEM word layout ---- */
#define A1_WORDS 32768                /* [ks][m][8] interleaved k-pairs: 128KB */
#define HT_PITCH 264                  /* words per n-row, packed (h0|h1)      */
#define HT_BUF   (8*HT_PITCH)         /* 2112 words per buffer                */
#define HT_OFF   A1_WORDS
#define SM_WORDS (A1_WORDS + 2*HT_BUF)
#define REC_SMEM (SM_WORDS*4)         /* 147968 bytes */

// ---------------- device scratch ------------------------------------------
__device__ float g_BA[HID*HID];
__device__ float g_BB[HID*HID];
__device__ float g_scale;
__device__ __align__(16) __nv_bfloat16 g_A0[HID*HID];  // bf16(A_norm), row-major
__device__ __align__(16) __nv_bfloat16 g_A1[HID*HID];  // bf16(A_norm - A0)
__device__ float g_WBT[CIN*HID];
__device__ float g_WCT[HID*COUT];
__device__ float g_u [(size_t)NROWS*HID];   // layout [t][b][h]
__device__ float g_hs[(size_t)NROWS*HID];   // layout [t][b][h]

// ---------------- HMMA helper ---------------------------------------------
__device__ __forceinline__ void mma_bf16(float c[4], const uint32_t a[4],
                                         uint32_t b0, uint32_t b1) {
    asm volatile(
        "mma.sync.aligned.m16n8k16.row.col.f32.bf16.bf16.f32 "
        "{%0,%1,%2,%3}, {%4,%5,%6,%7}, {%8,%9}, {%0,%1,%2,%3};\n"
        : "+f"(c[0]), "+f"(c[1]), "+f"(c[2]), "+f"(c[3])
        : "r"(a[0]), "r"(a[1]), "r"(a[2]), "r"(a[3]), "r"(b0), "r"(b1));
}

// ---------------- 1) B = A^T A --------------------------------------------
__global__ void k_ata(const float* __restrict__ A) {
    __shared__ float col[HID];
    int i = blockIdx.x, j = threadIdx.x;
    col[j] = A[j*HID + i];
    __syncthreads();
    float a0=0.f,a1=0.f,a2=0.f,a3=0.f;
    #pragma unroll 16
    for (int k = 0; k < HID; k += 4) {
        a0 = fmaf(col[k+0], A[(k+0)*HID + j], a0);
        a1 = fmaf(col[k+1], A[(k+1)*HID + j], a1);
        a2 = fmaf(col[k+2], A[(k+2)*HID + j], a2);
        a3 = fmaf(col[k+3], A[(k+3)*HID + j], a3);
    }
    g_BA[i*HID + j] = (a0+a1)+(a2+a3);
}

// ---------------- 2) B <- B@B (7x => B^128) -------------------------------
__global__ void k_sq(int srcA) {
    const float* __restrict__ Bin = srcA ? g_BA : g_BB;
    float* __restrict__ Bout      = srcA ? g_BB : g_BA;
    __shared__ float row[HID];
    int i = blockIdx.x, j = threadIdx.x;
    row[j] = Bin[i*HID + j];
    __syncthreads();
    float a0=0.f,a1=0.f,a2=0.f,a3=0.f;
    #pragma unroll 16
    for (int k = 0; k < HID; k += 4) {
        a0 = fmaf(row[k+0], Bin[(k+0)*HID + j], a0);
        a1 = fmaf(row[k+1], Bin[(k+1)*HID + j], a1);
        a2 = fmaf(row[k+2], Bin[(k+2)*HID + j], a2);
        a3 = fmaf(row[k+3], Bin[(k+3)*HID + j], a3);
    }
    Bout[i*HID + j] = (a0+a1)+(a2+a3);
}

// ---------------- 3) power iteration on C = B^128 -------------------------
__device__ float red_sum(float v, float* red, int tid) {
    red[tid] = v; __syncthreads();
    for (int s = 128; s > 0; s >>= 1) { if (tid < s) red[tid] += red[tid+s]; __syncthreads(); }
    float r = red[0]; __syncthreads(); return r;
}
__device__ float red_max(float v, float* red, int tid) {
    red[tid] = v; __syncthreads();
    for (int s = 128; s > 0; s >>= 1) { if (tid < s) red[tid] = fmaxf(red[tid], red[tid+s]); __syncthreads(); }
    float r = red[0]; __syncthreads(); return r;
}
__global__ void k_power() {
    __shared__ float v[HID];
    __shared__ float red[HID];
    int tid = threadIdx.x;
    const float* __restrict__ C = g_BB;
    v[tid] = 1.0f;
    __syncthreads();
    float w = 0.f;
    for (int it = 0; it < PITERS; ++it) {
        float a0=0.f,a1=0.f,a2=0.f,a3=0.f;
        #pragma unroll 8
        for (int k = 0; k < HID; k += 4) {
            a0 = fmaf(C[(k+0)*HID + tid], v[k+0], a0);
            a1 = fmaf(C[(k+1)*HID + tid], v[k+1], a1);
            a2 = fmaf(C[(k+2)*HID + tid], v[k+2], a2);
            a3 = fmaf(C[(k+3)*HID + tid], v[k+3], a3);
        }
        w = (a0+a1)+(a2+a3);
        float m = red_max(fabsf(w), red, tid);
        v[tid] = w * (1.0f/m);
        __syncthreads();
    }
    {
        float a0=0.f,a1=0.f,a2=0.f,a3=0.f;
        #pragma unroll 8
        for (int k = 0; k < HID; k += 4) {
            a0 = fmaf(C[(k+0)*HID + tid], v[k+0], a0);
            a1 = fmaf(C[(k+1)*HID + tid], v[k+1], a1);
            a2 = fmaf(C[(k+2)*HID + tid], v[k+2], a2);
            a3 = fmaf(C[(k+3)*HID + tid], v[k+3], a3);
        }
        w = (a0+a1)+(a2+a3);
    }
    float num = red_sum(v[tid]*w,      red, tid);
    float den = red_sum(v[tid]*v[tid], red, tid);
    if (tid == 0) {
        double mu = (double)num / (double)den;       // ~ sigma^256
        double sigma = exp(log(mu) / 256.0);
        g_scale = (float)(1.0 / (sigma + 1e-5));
    }
}

// ---------------- 4) prep: A0/A1 bf16 split, WBT, WCT ---------------------
__global__ void k_prep(const float* __restrict__ A,
                       const float* __restrict__ WB,
                       const float* __restrict__ WC) {
    int bi = blockIdx.x, tj = threadIdx.x;       // 256 x 256
    float s = g_scale;
    float an = A[bi*HID + tj] * s;
    __nv_bfloat16 a0 = __float2bfloat16(an);
    g_A0[bi*HID + tj] = a0;
    g_A1[bi*HID + tj] = __float2bfloat16(an - __bfloat162float(a0));
    if (bi < CIN)  g_WBT[bi*HID + tj]  = WB[tj*CIN + bi];
    if (tj < COUT) g_WCT[bi*COUT + tj] = WC[tj*HID + bi];
}

// ---------------- 5) u = x @ W_B^T  (writes [t][b][h]) --------------------
__global__ void __launch_bounds__(256) k_uproj(const float* __restrict__ x) {
    __shared__ float xs[CIN*36];
    int tid = threadIdx.x;
    size_t row0 = (size_t)blockIdx.x * 32;       // b-major row = b*SEQ + t
    for (int idx = tid; idx < 32*CIN; idx += 256) {
        int k = idx & 127, r = idx >> 7;
        xs[k*36 + r] = x[(row0 + r)*CIN + k];
    }
    __syncthreads();
    int j = tid;
    float acc[32];
    #pragma unroll
    for (int r = 0; r < 32; ++r) acc[r] = 0.f;
    #pragma unroll 2
    for (int k = 0; k < CIN; ++k) {
        float wb = g_WBT[k*HID + j];
        #pragma unroll
        for (int r = 0; r < 32; r += 4) {
            float4 xv = *(const float4*)&xs[k*36 + r];
            acc[r+0] = fmaf(wb, xv.x, acc[r+0]);
            acc[r+1] = fmaf(wb, xv.y, acc[r+1]);
            acc[r+2] = fmaf(wb, xv.z, acc[r+2]);
            acc[r+3] = fmaf(wb, xv.w, acc[r+3]);
        }
    }
    int b = (int)(row0 >> 12);
    int t_base = (int)(row0 & 4095);
    #pragma unroll
    for (int r = 0; r < 32; ++r)
        g_u[((size_t)(t_base + r)*BATCH + b)*HID + j] = acc[r];
}

// ---------------- 6) recurrence on mma.sync bf16 --------------------------
// 128 CTAs = 32 chunks x 4 batch-groups (NB=8). 256 threads = 8 warps.
// Warp w owns m-rows [32w,32w+32). D = A0.h0 + A0.h1 + A1.h0 into three
// independent accumulator sets. A0 reg-resident; A1 in SMEM [ks][m][8]
// (k-pair interleave -> LDS.64 fragments); h packed (h0|h1) per word.
__global__ void __launch_bounds__(256,1) k_rec() {
    extern __shared__ uint32_t sw[];
    const int tid = threadIdx.x;
    const int w = tid >> 5, l = tid & 31, g = l >> 2, tg = l & 3;
    const int wb = w * 32;
    const int chunk = blockIdx.x >> 2, bbase = (blockIdx.x & 3) * NB;

    // ---- A1 -> SMEM [ks][m][8], pairs interleaved [c0,c4,c1,c5,c2,c6,c3,c7]
    {
        const uint32_t* A1w = (const uint32_t*)g_A1;     // word = m*128 + kpair
        for (int p = tid; p < HID*HID/2; p += 256) {
            int m = p >> 7, kp = p & 127;
            int ks = kp >> 3, c = kp & 7;
            int pos = (c < 4) ? 2*c : 2*(c-4)+1;
            sw[ks*2048 + m*8 + pos] = A1w[p];
        }
    }
    // ---- zero hT (both buffers) => h(t0) = 0 ------------------------------
    for (int p = tid; p < 2*HT_BUF; p += 256) sw[HT_OFF + p] = 0;

    // ---- A0 fragments -> registers ----------------------------------------
    uint32_t a0f[2][16][4];
    {
        const uint32_t* A0w = (const uint32_t*)g_A0;
        #pragma unroll
        for (int mt = 0; mt < 2; ++mt) {
            int mr = wb + mt*16 + g;
            #pragma unroll
            for (int ks = 0; ks < 16; ++ks) {
                int base = 8*ks + tg;
                a0f[mt][ks][0] = A0w[(size_t)mr*128 + base];
                a0f[mt][ks][1] = A0w[(size_t)(mr+8)*128 + base];
                a0f[mt][ks][2] = A0w[(size_t)mr*128 + base + 4];
                a0f[mt][ks][3] = A0w[(size_t)(mr+8)*128 + base + 4];
            }
        }
    }
    __syncthreads();

    int t0 = chunk*CHUNK_LEN - WARM; if (t0 < 0) t0 = 0;
    const int t1 = chunk*CHUNK_LEN, tend = t1 + CHUNK_LEN;

    // preload u(t0)
    float ur[2][4];
    {
        const float* ub = g_u + ((size_t)t0*BATCH + bbase)*HID;
        #pragma unroll
        for (int mt = 0; mt < 2; ++mt) {
            int m0 = wb + mt*16 + g;
            #pragma unroll
            for (int q = 0; q < 4; ++q)
                ur[mt][q] = ub[(size_t)(2*tg + (q&1))*HID + m0 + ((q>>1)<<3)];
        }
    }

    int par = 0;
    for (int t = t0; t < tend; ++t, par ^= 1) {
        const uint32_t* hb = sw + HT_OFF + par*HT_BUF;
        uint32_t* wbuf     = sw + HT_OFF + (par^1)*HT_BUF;

        // prefetch u(t+1) early; DRAM latency hides under the MMA work
        float urn[2][4];
        {
            int tn = (t + 1 < tend) ? t + 1 : t;
            const float* ub = g_u + ((size_t)tn*BATCH + bbase)*HID;
            #pragma unroll
            for (int mt = 0; mt < 2; ++mt) {
                int m0 = wb + mt*16 + g;
                #pragma unroll
                for (int q = 0; q < 4; ++q)
                    urn[mt][q] = ub[(size_t)(2*tg + (q&1))*HID + m0 + ((q>>1)<<3)];
            }
        }

        float acc0[2][4] = {{0,0,0,0},{0,0,0,0}};
        float acc1[2][4] = {{0,0,0,0},{0,0,0,0}};
        float acc2[2][4] = {{0,0,0,0},{0,0,0,0}};
        #pragma unroll
        for (int ks = 0; ks < 16; ++ks) {
            const uint32_t* hrow = hb + g*HT_PITCH + 16*ks + 2*tg;
            uint2 hA = *(const uint2*)hrow;          // k = 2tg, 2tg+1 (packed h0|h1)
            uint2 hB = *(const uint2*)(hrow + 8);    // k = 2tg+8, 2tg+9
            uint32_t b00 = __byte_perm(hA.x, hA.y, 0x5410);
            uint32_t b10 = __byte_perm(hA.x, hA.y, 0x7632);
            uint32_t b01 = __byte_perm(hB.x, hB.y, 0x5410);
            uint32_t b11 = __byte_perm(hB.x, hB.y, 0x7632);
            const uint32_t* pan = sw + ks*2048;
            #pragma unroll
            for (int mt = 0; mt < 2; ++mt) {
                int mr = wb + mt*16 + g;
                uint2 rlo = *(const uint2*)(pan + mr*8 + 2*tg);       // (a0, a2)
                uint2 rhi = *(const uint2*)(pan + (mr+8)*8 + 2*tg);   // (a1, a3)
                uint32_t a1f[4] = {rlo.x, rhi.x, rlo.y, rhi.y};
                mma_bf16(acc0[mt], a0f[mt][ks], b00, b01);   // A0 . h0
                mma_bf16(acc1[mt], a0f[mt][ks], b10, b11);   // A0 . h1
                mma_bf16(acc2[mt], a1f,         b00, b01);   // A1 . h0
            }
        }

        // epilogue: relu(sum + u) -> packed bf16 split -> hT[wr]; hs store
        {
            bool emit = (t >= t1);
            float* hsb = g_hs + ((size_t)t*BATCH + bbase)*HID;
            #pragma unroll
            for (int mt = 0; mt < 2; ++mt) {
                #pragma unroll
                for (int q = 0; q < 4; ++q) {
                    int m = wb + mt*16 + g + ((q>>1)<<3);
                    int n = 2*tg + (q&1);
                    float hv = fmaxf(acc0[mt][q] + acc1[mt][q] + acc2[mt][q] + ur[mt][q], 0.f);
                    __nv_bfloat16 h0 = __float2bfloat16(hv);
                    __nv_bfloat16 h1 = __float2bfloat16(hv - __bfloat162float(h0));
                    wbuf[n*HT_PITCH + m] = (uint32_t)__bfloat16_as_ushort(h0)
                                         | ((uint32_t)__bfloat16_as_ushort(h1) << 16);
                    if (emit) hsb[(size_t)n*HID + m] = hv;
                }
            }
        }
        #pragma unroll
        for (int mt = 0; mt < 2; ++mt)
            #pragma unroll
            for (int q = 0; q < 4; ++q) ur[mt][q] = urn[mt][q];
        __syncthreads();
    }
}

// ---------------- 7) y = hs @ W_C^T  (reads [t][b][h]) --------------------
__global__ void __launch_bounds__(256) k_yproj(float* __restrict__ y) {
    __shared__ float hst[HID*36];
    int tid = threadIdx.x;
    size_t row0 = (size_t)blockIdx.x * 32;       // row = t*BATCH + b
    for (int idx = tid; idx < 32*HID; idx += 256) {
        int k = idx & 255, r = idx >> 8;
        hst[k*36 + r] = g_hs[(row0 + r)*HID + k];
    }
    __syncthreads();
    int j = tid & 127, rb = (tid >> 7) * 16;
    float acc[16];
    #pragma unroll
    for (int r = 0; r < 16; ++r) acc[r] = 0.f;
    #pragma unroll 2
    for (int k = 0; k < HID; ++k) {
        float wc = g_WCT[k*COUT + j];
        #pragma unroll
        for (int r = 0; r < 16; r += 4) {
            float4 hv = *(const float4*)&hst[k*36 + rb + r];
            acc[r+0] = fmaf(wc, hv.x, acc[r+0]);
            acc[r+1] = fmaf(wc, hv.y, acc[r+1]);
            acc[r+2] = fmaf(wc, hv.z, acc[r+2]);
            acc[r+3] = fmaf(wc, hv.w, acc[r+3]);
        }
    }
    int t = (int)(row0 >> 5);
    #pragma unroll
    for (int r = 0; r < 16; ++r) {
        int b = rb + r;
        y[((size_t)b*SEQ + t)*COUT + j] = acc[r];
    }
}

// ---------------- launch ---------------------------------------------------
extern "C" void kernel_launch(void* const* d_in, const int* in_sizes, int n_in,
                              void* d_out, int out_size) {
    const float* x  = (const float*)d_in[0];
    const float* A  = (const float*)d_in[1];
    const float* WB = (const float*)d_in[2];
    const float* WC = (const float*)d_in[3];
    float* y = (float*)d_out;

    cudaFuncSetAttribute(k_rec, cudaFuncAttributeMaxDynamicSharedMemorySize, REC_SMEM);

    k_ata<<<HID, HID>>>(A);
    k_sq<<<HID, HID>>>(1);
    k_sq<<<HID, HID>>>(0);
    k_sq<<<HID, HID>>>(1);
    k_sq<<<HID, HID>>>(0);
    k_sq<<<HID, HID>>>(1);
    k_sq<<<HID, HID>>>(0);
    k_sq<<<HID, HID>>>(1);            // C = B^128 in g_BB
    k_power<<<1, HID>>>();
    k_prep<<<HID, HID>>>(A, WB, WC);
    k_uproj<<<NROWS/32, 256>>>(x);
    k_rec<<<CHUNKS*(BATCH/NB), 256, REC_SMEM>>>();
    k_yproj<<<NROWS/32, 256>>>(y);
}

// round 13
// speedup vs baseline: 1.9296x; 1.1345x over previous
#include <cuda_runtime.h>
#include <cuda_bf16.h>
#include <math.h>
#include <stdint.h>

#define HID    256
#define CIN    128
#define COUT   128
#define BATCH  32
#define SEQ    4096
#define NROWS  (BATCH*SEQ)
#define CHUNKS 32
#define CHUNK_LEN (SEQ/CHUNKS)   /* 128 */
#define WARM   256
#define PITERS 32
#define NB     8                 /* batches per rec CTA */

/* ---- k_rec SMEM word layout ---- */
#define A1_WORDS 32768                /* fragment-major A1: 128KB            */
#define HT_PITCH 272                  /* words per n-row (==16 mod 32)       */
#define HT_BUF   (8*HT_PITCH)         /* 2176 words per buffer               */
#define HT_OFF   A1_WORDS
#define SM_WORDS (A1_WORDS + 2*HT_BUF)
#define REC_SMEM (SM_WORDS*4)         /* 148480 bytes */

// ---------------- device scratch ------------------------------------------
__device__ float g_BA[HID*HID];
__device__ float g_BB[HID*HID];
__device__ float g_scale;
__device__ __align__(16) __nv_bfloat16 g_A0[HID*HID];  // bf16(A_norm), row-major
__device__ __align__(16) __nv_bfloat16 g_A1[HID*HID];  // bf16(A_norm - A0)
__device__ float g_WBT[CIN*HID];
__device__ float g_WCT[HID*COUT];
__device__ float g_u [(size_t)NROWS*HID];   // layout [t][b][h]
__device__ float g_hs[(size_t)NROWS*HID];   // layout [t][b][h]

// ---------------- HMMA helper ---------------------------------------------
__device__ __forceinline__ void mma_bf16(float c[4], const uint32_t a[4],
                                         uint32_t b0, uint32_t b1) {
    asm volatile(
        "mma.sync.aligned.m16n8k16.row.col.f32.bf16.bf16.f32 "
        "{%0,%1,%2,%3}, {%4,%5,%6,%7}, {%8,%9}, {%0,%1,%2,%3};\n"
        : "+f"(c[0]), "+f"(c[1]), "+f"(c[2]), "+f"(c[3])
        : "r"(a[0]), "r"(a[1]), "r"(a[2]), "r"(a[3]), "r"(b0), "r"(b1));
}

// ---------------- 1) B = A^T A --------------------------------------------
__global__ void k_ata(const float* __restrict__ A) {
    __shared__ float col[HID];
    int i = blockIdx.x, j = threadIdx.x;
    col[j] = A[j*HID + i];
    __syncthreads();
    float a0=0.f,a1=0.f,a2=0.f,a3=0.f;
    #pragma unroll 16
    for (int k = 0; k < HID; k += 4) {
        a0 = fmaf(col[k+0], A[(k+0)*HID + j], a0);
        a1 = fmaf(col[k+1], A[(k+1)*HID + j], a1);
        a2 = fmaf(col[k+2], A[(k+2)*HID + j], a2);
        a3 = fmaf(col[k+3], A[(k+3)*HID + j], a3);
    }
    g_BA[i*HID + j] = (a0+a1)+(a2+a3);
}

// ---------------- 2) B <- B@B (7x => B^128) -------------------------------
__global__ void k_sq(int srcA) {
    const float* __restrict__ Bin = srcA ? g_BA : g_BB;
    float* __restrict__ Bout      = srcA ? g_BB : g_BA;
    __shared__ float row[HID];
    int i = blockIdx.x, j = threadIdx.x;
    row[j] = Bin[i*HID + j];
    __syncthreads();
    float a0=0.f,a1=0.f,a2=0.f,a3=0.f;
    #pragma unroll 16
    for (int k = 0; k < HID; k += 4) {
        a0 = fmaf(row[k+0], Bin[(k+0)*HID + j], a0);
        a1 = fmaf(row[k+1], Bin[(k+1)*HID + j], a1);
        a2 = fmaf(row[k+2], Bin[(k+2)*HID + j], a2);
        a3 = fmaf(row[k+3], Bin[(k+3)*HID + j], a3);
    }
    Bout[i*HID + j] = (a0+a1)+(a2+a3);
}

// ---------------- 3) power iteration on C = B^128 -------------------------
__device__ float red_sum(float v, float* red, int tid) {
    red[tid] = v; __syncthreads();
    for (int s = 128; s > 0; s >>= 1) { if (tid < s) red[tid] += red[tid+s]; __syncthreads(); }
    float r = red[0]; __syncthreads(); return r;
}
__device__ float red_max(float v, float* red, int tid) {
    red[tid] = v; __syncthreads();
    for (int s = 128; s > 0; s >>= 1) { if (tid < s) red[tid] = fmaxf(red[tid], red[tid+s]); __syncthreads(); }
    float r = red[0]; __syncthreads(); return r;
}
__global__ void k_power() {
    __shared__ float v[HID];
    __shared__ float red[HID];
    int tid = threadIdx.x;
    const float* __restrict__ C = g_BB;
    v[tid] = 1.0f;
    __syncthreads();
    float w = 0.f;
    for (int it = 0; it < PITERS; ++it) {
        float a0=0.f,a1=0.f,a2=0.f,a3=0.f;
        #pragma unroll 8
        for (int k = 0; k < HID; k += 4) {
            a0 = fmaf(C[(k+0)*HID + tid], v[k+0], a0);
            a1 = fmaf(C[(k+1)*HID + tid], v[k+1], a1);
            a2 = fmaf(C[(k+2)*HID + tid], v[k+2], a2);
            a3 = fmaf(C[(k+3)*HID + tid], v[k+3], a3);
        }
        w = (a0+a1)+(a2+a3);
        float m = red_max(fabsf(w), red, tid);
        v[tid] = w * (1.0f/m);
        __syncthreads();
    }
    {
        float a0=0.f,a1=0.f,a2=0.f,a3=0.f;
        #pragma unroll 8
        for (int k = 0; k < HID; k += 4) {
            a0 = fmaf(C[(k+0)*HID + tid], v[k+0], a0);
            a1 = fmaf(C[(k+1)*HID + tid], v[k+1], a1);
            a2 = fmaf(C[(k+2)*HID + tid], v[k+2], a2);
            a3 = fmaf(C[(k+3)*HID + tid], v[k+3], a3);
        }
        w = (a0+a1)+(a2+a3);
    }
    float num = red_sum(v[tid]*w,      red, tid);
    float den = red_sum(v[tid]*v[tid], red, tid);
    if (tid == 0) {
        double mu = (double)num / (double)den;       // ~ sigma^256
        double sigma = exp(log(mu) / 256.0);
        g_scale = (float)(1.0 / (sigma + 1e-5));
    }
}

// ---------------- 4) prep: A0/A1 bf16 split, WBT, WCT ---------------------
__global__ void k_prep(const float* __restrict__ A,
                       const float* __restrict__ WB,
                       const float* __restrict__ WC) {
    int bi = blockIdx.x, tj = threadIdx.x;       // 256 x 256
    float s = g_scale;
    float an = A[bi*HID + tj] * s;
    __nv_bfloat16 a0 = __float2bfloat16(an);
    g_A0[bi*HID + tj] = a0;
    g_A1[bi*HID + tj] = __float2bfloat16(an - __bfloat162float(a0));
    if (bi < CIN)  g_WBT[bi*HID + tj]  = WB[tj*CIN + bi];
    if (tj < COUT) g_WCT[bi*COUT + tj] = WC[tj*HID + bi];
}

// ---------------- 5) u = x @ W_B^T  (writes [t][b][h]) --------------------
__global__ void __launch_bounds__(256) k_uproj(const float* __restrict__ x) {
    __shared__ float xs[CIN*36];
    int tid = threadIdx.x;
    size_t row0 = (size_t)blockIdx.x * 32;       // b-major row = b*SEQ + t
    for (int idx = tid; idx < 32*CIN; idx += 256) {
        int k = idx & 127, r = idx >> 7;
        xs[k*36 + r] = x[(row0 + r)*CIN + k];
    }
    __syncthreads();
    int j = tid;
    float acc[32];
    #pragma unroll
    for (int r = 0; r < 32; ++r) acc[r] = 0.f;
    #pragma unroll 2
    for (int k = 0; k < CIN; ++k) {
        float wb = g_WBT[k*HID + j];
        #pragma unroll
        for (int r = 0; r < 32; r += 4) {
            float4 xv = *(const float4*)&xs[k*36 + r];
            acc[r+0] = fmaf(wb, xv.x, acc[r+0]);
            acc[r+1] = fmaf(wb, xv.y, acc[r+1]);
            acc[r+2] = fmaf(wb, xv.z, acc[r+2]);
            acc[r+3] = fmaf(wb, xv.w, acc[r+3]);
        }
    }
    int b = (int)(row0 >> 12);
    int t_base = (int)(row0 & 4095);
    #pragma unroll
    for (int r = 0; r < 32; ++r)
        g_u[((size_t)(t_base + r)*BATCH + b)*HID + j] = acc[r];
}

// ---------------- 6) recurrence on mma.sync bf16 --------------------------
// 128 CTAs = 32 chunks x 4 batch-groups (NB=8). 256 threads = 8 warps.
// Warp w owns m-rows [32w,32w+32), full K. D = A0.h0 + A0.h1 + A1.h0 into
// three independent accumulator sets. A0 reg-resident; A1 fragment-major in
// SMEM (one LDS.128 per (ks,mt)); h packed (h0|h1), fragment-major order
// (one LDS.128 per ks).
__global__ void __launch_bounds__(256,1) k_rec() {
    extern __shared__ uint32_t sw[];
    const int tid = threadIdx.x;
    const int w = tid >> 5, l = tid & 31, g = l >> 2, tg = l & 3;
    const int wb = w * 32;
    const int chunk = blockIdx.x >> 2, bbase = (blockIdx.x & 3) * NB;

    // ---- A1 -> SMEM fragment-major: word ((ks*16+mtile)*32+l)*4 + c ------
    {
        const uint32_t* A1w = (const uint32_t*)g_A1;     // word = m*128 + kpair
        for (int p = tid; p < HID*HID/2; p += 256) {
            int m = p >> 7, kp = p & 127;
            int ks = kp >> 3, tgc = kp & 7;
            int tg_ = tgc & 3, ch = tgc >> 2;            // kpair half
            int mtile = m >> 4, gg = m & 15;
            int g_ = gg & 7, mh = gg >> 3;               // row half
            int c  = ch*2 + mh;
            int l_ = g_*4 + tg_;
            sw[((ks*16 + mtile)*32 + l_)*4 + c] = A1w[p];
        }
    }
    // ---- zero hT (both buffers) => h(t0) = 0 ------------------------------
    for (int p = tid; p < 2*HT_BUF; p += 256) sw[HT_OFF + p] = 0;

    // ---- A0 fragments -> registers ----------------------------------------
    uint32_t a0f[2][16][4];
    {
        const uint32_t* A0w = (const uint32_t*)g_A0;
        #pragma unroll
        for (int mt = 0; mt < 2; ++mt) {
            int mr = wb + mt*16 + g;
            #pragma unroll
            for (int ks = 0; ks < 16; ++ks) {
                int base = 8*ks + tg;
                a0f[mt][ks][0] = A0w[(size_t)mr*128 + base];
                a0f[mt][ks][1] = A0w[(size_t)(mr+8)*128 + base];
                a0f[mt][ks][2] = A0w[(size_t)mr*128 + base + 4];
                a0f[mt][ks][3] = A0w[(size_t)(mr+8)*128 + base + 4];
            }
        }
    }
    __syncthreads();

    int t0 = chunk*CHUNK_LEN - WARM; if (t0 < 0) t0 = 0;
    const int t1 = chunk*CHUNK_LEN, tend = t1 + CHUNK_LEN;

    // preload u(t0)
    float ur[2][4];
    {
        const float* ub = g_u + ((size_t)t0*BATCH + bbase)*HID;
        #pragma unroll
        for (int mt = 0; mt < 2; ++mt) {
            int m0 = wb + mt*16 + g;
            #pragma unroll
            for (int q = 0; q < 4; ++q)
                ur[mt][q] = ub[(size_t)(2*tg + (q&1))*HID + m0 + ((q>>1)<<3)];
        }
    }

    int par = 0;
    for (int t = t0; t < tend; ++t, par ^= 1) {
        const uint32_t* hb = sw + HT_OFF + par*HT_BUF;
        uint32_t* wbuf     = sw + HT_OFF + (par^1)*HT_BUF;

        // prefetch u(t+1); DRAM latency hides under the MMA work
        float urn[2][4];
        {
            int tn = (t + 1 < tend) ? t + 1 : t;
            const float* ub = g_u + ((size_t)tn*BATCH + bbase)*HID;
            #pragma unroll
            for (int mt = 0; mt < 2; ++mt) {
                int m0 = wb + mt*16 + g;
                #pragma unroll
                for (int q = 0; q < 4; ++q)
                    urn[mt][q] = ub[(size_t)(2*tg + (q&1))*HID + m0 + ((q>>1)<<3)];
            }
        }

        float acc0[2][4] = {{0,0,0,0},{0,0,0,0}};
        float acc1[2][4] = {{0,0,0,0},{0,0,0,0}};
        float acc2[2][4] = {{0,0,0,0},{0,0,0,0}};
        const uint32_t* hrow = hb + g*HT_PITCH + 4*tg;
        #pragma unroll
        for (int ks = 0; ks < 16; ++ks) {
            uint4 hv = *(const uint4*)(hrow + 16*ks);
            uint32_t b00 = __byte_perm(hv.x, hv.y, 0x5410);
            uint32_t b10 = __byte_perm(hv.x, hv.y, 0x7632);
            uint32_t b01 = __byte_perm(hv.z, hv.w, 0x5410);
            uint32_t b11 = __byte_perm(hv.z, hv.w, 0x7632);
            #pragma unroll
            for (int mt = 0; mt < 2; ++mt) {
                int mtile = 2*w + mt;
                uint4 af = *(const uint4*)(sw + ((ks*16 + mtile)*32 + l)*4);
                uint32_t a1f[4] = {af.x, af.y, af.z, af.w};
                mma_bf16(acc0[mt], a0f[mt][ks], b00, b01);   // A0 . h0
                mma_bf16(acc1[mt], a0f[mt][ks], b10, b11);   // A0 . h1
                mma_bf16(acc2[mt], a1f,         b00, b01);   // A1 . h0
            }
        }

        // epilogue: relu(sum + u) -> packed bf16 split -> fragment-major hT
        {
            bool emit = (t >= t1);
            float* hsb = g_hs + ((size_t)t*BATCH + bbase)*HID;
            #pragma unroll
            for (int mt = 0; mt < 2; ++mt) {
                #pragma unroll
                for (int q = 0; q < 4; ++q) {
                    int m = wb + mt*16 + g + ((q>>1)<<3);
                    int n = 2*tg + (q&1);
                    float hv = fmaxf(acc0[mt][q] + acc1[mt][q] + acc2[mt][q] + ur[mt][q], 0.f);
                    __nv_bfloat16 h0 = __float2bfloat16(hv);
                    __nv_bfloat16 h1 = __float2bfloat16(hv - __bfloat162float(h0));
                    int r = m & 15;
                    int pos = 16*(m >> 4) + 4*((r & 7) >> 1) + (r & 1) + 2*(r >> 3);
                    wbuf[n*HT_PITCH + pos] = (uint32_t)__bfloat16_as_ushort(h0)
                                           | ((uint32_t)__bfloat16_as_ushort(h1) << 16);
                    if (emit) hsb[(size_t)n*HID + m] = hv;
                }
            }
        }
        #pragma unroll
        for (int mt = 0; mt < 2; ++mt)
            #pragma unroll
            for (int q = 0; q < 4; ++q) ur[mt][q] = urn[mt][q];
        __syncthreads();
    }
}

// ---------------- 7) y = hs @ W_C^T  (reads [t][b][h]) --------------------
__global__ void __launch_bounds__(256) k_yproj(float* __restrict__ y) {
    __shared__ float hst[HID*36];
    int tid = threadIdx.x;
    size_t row0 = (size_t)blockIdx.x * 32;       // row = t*BATCH + b
    for (int idx = tid; idx < 32*HID; idx += 256) {
        int k = idx & 255, r = idx >> 8;
        hst[k*36 + r] = g_hs[(row0 + r)*HID + k];
    }
    __syncthreads();
    int j = tid & 127, rb = (tid >> 7) * 16;
    float acc[16];
    #pragma unroll
    for (int r = 0; r < 16; ++r) acc[r] = 0.f;
    #pragma unroll 2
    for (int k = 0; k < HID; ++k) {
        float wc = g_WCT[k*COUT + j];
        #pragma unroll
        for (int r = 0; r < 16; r += 4) {
            float4 hv = *(const float4*)&hst[k*36 + rb + r];
            acc[r+0] = fmaf(wc, hv.x, acc[r+0]);
            acc[r+1] = fmaf(wc, hv.y, acc[r+1]);
            acc[r+2] = fmaf(wc, hv.z, acc[r+2]);
            acc[r+3] = fmaf(wc, hv.w, acc[r+3]);
        }
    }
    int t = (int)(row0 >> 5);
    #pragma unroll
    for (int r = 0; r < 16; ++r) {
        int b = rb + r;
        y[((size_t)b*SEQ + t)*COUT + j] = acc[r];
    }
}

// ---------------- launch ---------------------------------------------------
extern "C" void kernel_launch(void* const* d_in, const int* in_sizes, int n_in,
                              void* d_out, int out_size) {
    const float* x  = (const float*)d_in[0];
    const float* A  = (const float*)d_in[1];
    const float* WB = (const float*)d_in[2];
    const float* WC = (const float*)d_in[3];
    float* y = (float*)d_out;

    cudaFuncSetAttribute(k_rec, cudaFuncAttributeMaxDynamicSharedMemorySize, REC_SMEM);

    k_ata<<<HID, HID>>>(A);
    k_sq<<<HID, HID>>>(1);
    k_sq<<<HID, HID>>>(0);
    k_sq<<<HID, HID>>>(1);
    k_sq<<<HID, HID>>>(0);
    k_sq<<<HID, HID>>>(1);
    k_sq<<<HID, HID>>>(0);
    k_sq<<<HID, HID>>>(1);            // C = B^128 in g_BB
    k_power<<<1, HID>>>();
    k_prep<<<HID, HID>>>(A, WB, WC);
    k_uproj<<<NROWS/32, 256>>>(x);
    k_rec<<<CHUNKS*(BATCH/NB), 256, REC_SMEM>>>();
    k_yproj<<<NROWS/32, 256>>>(y);
}

// round 14
// speedup vs baseline: 2.2092x; 1.1449x over previous
#include <cuda_runtime.h>
#include <cuda_bf16.h>
#include <math.h>
#include <stdint.h>

#define HID    256
#define CIN    128
#define COUT   128
#define BATCH  32
#define SEQ    4096
#define NROWS  (BATCH*SEQ)
#define CHUNKS 32
#define CHUNK_LEN (SEQ/CHUNKS)   /* 128 */
#define WARM   128
#define PITERS 32
#define NB     8                 /* batches per rec CTA */

/* ---- k_rec SMEM word layout (R12-proven) ---- */
#define A1_WORDS 32768                /* [ks][m][8] interleaved k-pairs: 128KB */
#define HT_PITCH 264                  /* words per n-row, packed (h0|h1)      */
#define HT_BUF   (8*HT_PITCH)         /* 2112 words per buffer                */
#define HT_OFF   A1_WORDS
#define SM_WORDS (A1_WORDS + 2*HT_BUF)
#define REC_SMEM (SM_WORDS*4)         /* 147968 bytes */

// ---------------- device scratch ------------------------------------------
__device__ float g_BA[HID*HID];
__device__ float g_BB[HID*HID];
__device__ float g_scale;
__device__ __align__(16) __nv_bfloat16 g_A0[HID*HID];  // bf16(A_norm), row-major
__device__ __align__(16) __nv_bfloat16 g_A1[HID*HID];  // bf16(A_norm - A0)
__device__ float g_WBT[CIN*HID];
__device__ float g_WCT[HID*COUT];
__device__ float g_u [(size_t)NROWS*HID];   // layout [t][b][h]
__device__ float g_hs[(size_t)NROWS*HID];   // layout [t][b][h]

// ---------------- HMMA helper ---------------------------------------------
__device__ __forceinline__ void mma_bf16(float c[4], const uint32_t a[4],
                                         uint32_t b0, uint32_t b1) {
    asm volatile(
        "mma.sync.aligned.m16n8k16.row.col.f32.bf16.bf16.f32 "
        "{%0,%1,%2,%3}, {%4,%5,%6,%7}, {%8,%9}, {%0,%1,%2,%3};\n"
        : "+f"(c[0]), "+f"(c[1]), "+f"(c[2]), "+f"(c[3])
        : "r"(a[0]), "r"(a[1]), "r"(a[2]), "r"(a[3]), "r"(b0), "r"(b1));
}

// ---------------- 1) B = A^T A --------------------------------------------
__global__ void k_ata(const float* __restrict__ A) {
    __shared__ float col[HID];
    int i = blockIdx.x, j = threadIdx.x;
    col[j] = A[j*HID + i];
    __syncthreads();
    float a0=0.f,a1=0.f,a2=0.f,a3=0.f;
    #pragma unroll 16
    for (int k = 0; k < HID; k += 4) {
        a0 = fmaf(col[k+0], A[(k+0)*HID + j], a0);
        a1 = fmaf(col[k+1], A[(k+1)*HID + j], a1);
        a2 = fmaf(col[k+2], A[(k+2)*HID + j], a2);
        a3 = fmaf(col[k+3], A[(k+3)*HID + j], a3);
    }
    g_BA[i*HID + j] = (a0+a1)+(a2+a3);
}

// ---------------- 2) B <- B@B (7x => B^128) -------------------------------
__global__ void k_sq(int srcA) {
    const float* __restrict__ Bin = srcA ? g_BA : g_BB;
    float* __restrict__ Bout      = srcA ? g_BB : g_BA;
    __shared__ float row[HID];
    int i = blockIdx.x, j = threadIdx.x;
    row[j] = Bin[i*HID + j];
    __syncthreads();
    float a0=0.f,a1=0.f,a2=0.f,a3=0.f;
    #pragma unroll 16
    for (int k = 0; k < HID; k += 4) {
        a0 = fmaf(row[k+0], Bin[(k+0)*HID + j], a0);
        a1 = fmaf(row[k+1], Bin[(k+1)*HID + j], a1);
        a2 = fmaf(row[k+2], Bin[(k+2)*HID + j], a2);
        a3 = fmaf(row[k+3], Bin[(k+3)*HID + j], a3);
    }
    Bout[i*HID + j] = (a0+a1)+(a2+a3);
}

// ---------------- 3) power iteration on C = B^128 -------------------------
__device__ float red_sum(float v, float* red, int tid) {
    red[tid] = v; __syncthreads();
    for (int s = 128; s > 0; s >>= 1) { if (tid < s) red[tid] += red[tid+s]; __syncthreads(); }
    float r = red[0]; __syncthreads(); return r;
}
__device__ float red_max(float v, float* red, int tid) {
    red[tid] = v; __syncthreads();
    for (int s = 128; s > 0; s >>= 1) { if (tid < s) red[tid] = fmaxf(red[tid], red[tid+s]); __syncthreads(); }
    float r = red[0]; __syncthreads(); return r;
}
__global__ void k_power() {
    __shared__ float v[HID];
    __shared__ float red[HID];
    int tid = threadIdx.x;
    const float* __restrict__ C = g_BB;
    v[tid] = 1.0f;
    __syncthreads();
    float w = 0.f;
    for (int it = 0; it < PITERS; ++it) {
        float a0=0.f,a1=0.f,a2=0.f,a3=0.f;
        #pragma unroll 8
        for (int k = 0; k < HID; k += 4) {
            a0 = fmaf(C[(k+0)*HID + tid], v[k+0], a0);
            a1 = fmaf(C[(k+1)*HID + tid], v[k+1], a1);
            a2 = fmaf(C[(k+2)*HID + tid], v[k+2], a2);
            a3 = fmaf(C[(k+3)*HID + tid], v[k+3], a3);
        }
        w = (a0+a1)+(a2+a3);
        float m = red_max(fabsf(w), red, tid);
        v[tid] = w * (1.0f/m);
        __syncthreads();
    }
    {
        float a0=0.f,a1=0.f,a2=0.f,a3=0.f;
        #pragma unroll 8
        for (int k = 0; k < HID; k += 4) {
            a0 = fmaf(C[(k+0)*HID + tid], v[k+0], a0);
            a1 = fmaf(C[(k+1)*HID + tid], v[k+1], a1);
            a2 = fmaf(C[(k+2)*HID + tid], v[k+2], a2);
            a3 = fmaf(C[(k+3)*HID + tid], v[k+3], a3);
        }
        w = (a0+a1)+(a2+a3);
    }
    float num = red_sum(v[tid]*w,      red, tid);
    float den = red_sum(v[tid]*v[tid], red, tid);
    if (tid == 0) {
        double mu = (double)num / (double)den;       // ~ sigma^256
        double sigma = exp(log(mu) / 256.0);
        g_scale = (float)(1.0 / (sigma + 1e-5));
    }
}

// ---------------- 4) prep: A0/A1 bf16 split, WBT, WCT ---------------------
__global__ void k_prep(const float* __restrict__ A,
                       const float* __restrict__ WB,
                       const float* __restrict__ WC) {
    int bi = blockIdx.x, tj = threadIdx.x;       // 256 x 256
    float s = g_scale;
    float an = A[bi*HID + tj] * s;
    __nv_bfloat16 a0 = __float2bfloat16(an);
    g_A0[bi*HID + tj] = a0;
    g_A1[bi*HID + tj] = __float2bfloat16(an - __bfloat162float(a0));
    if (bi < CIN)  g_WBT[bi*HID + tj]  = WB[tj*CIN + bi];
    if (tj < COUT) g_WCT[bi*COUT + tj] = WC[tj*HID + bi];
}

// ---------------- 5) u = x @ W_B^T  (writes [t][b][h]) --------------------
__global__ void __launch_bounds__(256) k_uproj(const float* __restrict__ x) {
    __shared__ float xs[CIN*36];
    int tid = threadIdx.x;
    size_t row0 = (size_t)blockIdx.x * 32;       // b-major row = b*SEQ + t
    for (int idx = tid; idx < 32*CIN; idx += 256) {
        int k = idx & 127, r = idx >> 7;
        xs[k*36 + r] = x[(row0 + r)*CIN + k];
    }
    __syncthreads();
    int j = tid;
    float acc[32];
    #pragma unroll
    for (int r = 0; r < 32; ++r) acc[r] = 0.f;
    #pragma unroll 2
    for (int k = 0; k < CIN; ++k) {
        float wb = g_WBT[k*HID + j];
        #pragma unroll
        for (int r = 0; r < 32; r += 4) {
            float4 xv = *(const float4*)&xs[k*36 + r];
            acc[r+0] = fmaf(wb, xv.x, acc[r+0]);
            acc[r+1] = fmaf(wb, xv.y, acc[r+1]);
            acc[r+2] = fmaf(wb, xv.z, acc[r+2]);
            acc[r+3] = fmaf(wb, xv.w, acc[r+3]);
        }
    }
    int b = (int)(row0 >> 12);
    int t_base = (int)(row0 & 4095);
    #pragma unroll
    for (int r = 0; r < 32; ++r)
        g_u[((size_t)(t_base + r)*BATCH + b)*HID + j] = acc[r];
}

// ---------------- 6) recurrence on mma.sync bf16 (R12-proven loop) --------
// 128 CTAs = 32 chunks x 4 batch-groups (NB=8). 256 threads = 8 warps.
// Warp w owns m-rows [32w,32w+32). D = A0.h0 + A0.h1 + A1.h0 into three
// independent accumulator sets. A0 reg-resident; A1 in SMEM [ks][m][8]
// (k-pair interleave -> LDS.64 fragments); h packed (h0|h1) per word.
__global__ void __launch_bounds__(256,1) k_rec() {
    extern __shared__ uint32_t sw[];
    const int tid = threadIdx.x;
    const int w = tid >> 5, l = tid & 31, g = l >> 2, tg = l & 3;
    const int wb = w * 32;
    const int chunk = blockIdx.x >> 2, bbase = (blockIdx.x & 3) * NB;

    // ---- A1 -> SMEM [ks][m][8], pairs interleaved [c0,c4,c1,c5,c2,c6,c3,c7]
    {
        const uint32_t* A1w = (const uint32_t*)g_A1;     // word = m*128 + kpair
        for (int p = tid; p < HID*HID/2; p += 256) {
            int m = p >> 7, kp = p & 127;
            int ks = kp >> 3, c = kp & 7;
            int pos = (c < 4) ? 2*c : 2*(c-4)+1;
            sw[ks*2048 + m*8 + pos] = A1w[p];
        }
    }
    // ---- zero hT (both buffers) => h(t0) = 0 ------------------------------
    for (int p = tid; p < 2*HT_BUF; p += 256) sw[HT_OFF + p] = 0;

    // ---- A0 fragments -> registers ----------------------------------------
    uint32_t a0f[2][16][4];
    {
        const uint32_t* A0w = (const uint32_t*)g_A0;
        #pragma unroll
        for (int mt = 0; mt < 2; ++mt) {
            int mr = wb + mt*16 + g;
            #pragma unroll
            for (int ks = 0; ks < 16; ++ks) {
                int base = 8*ks + tg;
                a0f[mt][ks][0] = A0w[(size_t)mr*128 + base];
                a0f[mt][ks][1] = A0w[(size_t)(mr+8)*128 + base];
                a0f[mt][ks][2] = A0w[(size_t)mr*128 + base + 4];
                a0f[mt][ks][3] = A0w[(size_t)(mr+8)*128 + base + 4];
            }
        }
    }
    __syncthreads();

    int t0 = chunk*CHUNK_LEN - WARM; if (t0 < 0) t0 = 0;
    const int t1 = chunk*CHUNK_LEN, tend = t1 + CHUNK_LEN;

    // preload u(t0)
    float ur[2][4];
    {
        const float* ub = g_u + ((size_t)t0*BATCH + bbase)*HID;
        #pragma unroll
        for (int mt = 0; mt < 2; ++mt) {
            int m0 = wb + mt*16 + g;
            #pragma unroll
            for (int q = 0; q < 4; ++q)
                ur[mt][q] = ub[(size_t)(2*tg + (q&1))*HID + m0 + ((q>>1)<<3)];
        }
    }

    int par = 0;
    for (int t = t0; t < tend; ++t, par ^= 1) {
        const uint32_t* hb = sw + HT_OFF + par*HT_BUF;
        uint32_t* wbuf     = sw + HT_OFF + (par^1)*HT_BUF;

        // prefetch u(t+1); DRAM latency hides under the MMA work
        float urn[2][4];
        {
            int tn = (t + 1 < tend) ? t + 1 : t;
            const float* ub = g_u + ((size_t)tn*BATCH + bbase)*HID;
            #pragma unroll
            for (int mt = 0; mt < 2; ++mt) {
                int m0 = wb + mt*16 + g;
                #pragma unroll
                for (int q = 0; q < 4; ++q)
                    urn[mt][q] = ub[(size_t)(2*tg + (q&1))*HID + m0 + ((q>>1)<<3)];
            }
        }

        float acc0[2][4] = {{0,0,0,0},{0,0,0,0}};
        float acc1[2][4] = {{0,0,0,0},{0,0,0,0}};
        float acc2[2][4] = {{0,0,0,0},{0,0,0,0}};
        #pragma unroll
        for (int ks = 0; ks < 16; ++ks) {
            const uint32_t* hrow = hb + g*HT_PITCH + 16*ks + 2*tg;
            uint2 hA = *(const uint2*)hrow;          // k = 2tg, 2tg+1 (packed h0|h1)
            uint2 hB = *(const uint2*)(hrow + 8);    // k = 2tg+8, 2tg+9
            uint32_t b00 = __byte_perm(hA.x, hA.y, 0x5410);
            uint32_t b10 = __byte_perm(hA.x, hA.y, 0x7632);
            uint32_t b01 = __byte_perm(hB.x, hB.y, 0x5410);
            uint32_t b11 = __byte_perm(hB.x, hB.y, 0x7632);
            const uint32_t* pan = sw + ks*2048;
            #pragma unroll
            for (int mt = 0; mt < 2; ++mt) {
                int mr = wb + mt*16 + g;
                uint2 rlo = *(const uint2*)(pan + mr*8 + 2*tg);       // (a0, a2)
                uint2 rhi = *(const uint2*)(pan + (mr+8)*8 + 2*tg);   // (a1, a3)
                uint32_t a1f[4] = {rlo.x, rhi.x, rlo.y, rhi.y};
                mma_bf16(acc0[mt], a0f[mt][ks], b00, b01);   // A0 . h0
                mma_bf16(acc1[mt], a0f[mt][ks], b10, b11);   // A0 . h1
                mma_bf16(acc2[mt], a1f,         b00, b01);   // A1 . h0
            }
        }

        // epilogue: relu(sum + u) -> packed bf16 split -> hT[wr]; hs store
        {
            bool emit = (t >= t1);
            float* hsb = g_hs + ((size_t)t*BATCH + bbase)*HID;
            #pragma unroll
            for (int mt = 0; mt < 2; ++mt) {
                #pragma unroll
                for (int q = 0; q < 4; ++q) {
                    int m = wb + mt*16 + g + ((q>>1)<<3);
                    int n = 2*tg + (q&1);
                    float hv = fmaxf(acc0[mt][q] + acc1[mt][q] + acc2[mt][q] + ur[mt][q], 0.f);
                    __nv_bfloat16 h0 = __float2bfloat16(hv);
                    __nv_bfloat16 h1 = __float2bfloat16(hv - __bfloat162float(h0));
                    wbuf[n*HT_PITCH + m] = (uint32_t)__bfloat16_as_ushort(h0)
                                         | ((uint32_t)__bfloat16_as_ushort(h1) << 16);
                    if (emit) hsb[(size_t)n*HID + m] = hv;
                }
            }
        }
        #pragma unroll
        for (int mt = 0; mt < 2; ++mt)
            #pragma unroll
            for (int q = 0; q < 4; ++q) ur[mt][q] = urn[mt][q];
        __syncthreads();
    }
}

// ---------------- 7) y = hs @ W_C^T  (reads [t][b][h]) --------------------
__global__ void __launch_bounds__(256) k_yproj(float* __restrict__ y) {
    __shared__ float hst[HID*36];
    int tid = threadIdx.x;
    size_t row0 = (size_t)blockIdx.x * 32;       // row = t*BATCH + b
    for (int idx = tid; idx < 32*HID; idx += 256) {
        int k = idx & 255, r = idx >> 8;
        hst[k*36 + r] = g_hs[(row0 + r)*HID + k];
    }
    __syncthreads();
    int j = tid & 127, rb = (tid >> 7) * 16;
    float acc[16];
    #pragma unroll
    for (int r = 0; r < 16; ++r) acc[r] = 0.f;
    #pragma unroll 2
    for (int k = 0; k < HID; ++k) {
        float wc = g_WCT[k*COUT + j];
        #pragma unroll
        for (int r = 0; r < 16; r += 4) {
            float4 hv = *(const float4*)&hst[k*36 + rb + r];
            acc[r+0] = fmaf(wc, hv.x, acc[r+0]);
            acc[r+1] = fmaf(wc, hv.y, acc[r+1]);
            acc[r+2] = fmaf(wc, hv.z, acc[r+2]);
            acc[r+3] = fmaf(wc, hv.w, acc[r+3]);
        }
    }
    int t = (int)(row0 >> 5);
    #pragma unroll
    for (int r = 0; r < 16; ++r) {
        int b = rb + r;
        y[((size_t)b*SEQ + t)*COUT + j] = acc[r];
    }
}

// ---------------- launch ---------------------------------------------------
extern "C" void kernel_launch(void* const* d_in, const int* in_sizes, int n_in,
                              void* d_out, int out_size) {
    const float* x  = (const float*)d_in[0];
    const float* A  = (const float*)d_in[1];
    const float* WB = (const float*)d_in[2];
    const float* WC = (const float*)d_in[3];
    float* y = (float*)d_out;

    cudaFuncSetAttribute(k_rec, cudaFuncAttributeMaxDynamicSharedMemorySize, REC_SMEM);

    k_ata<<<HID, HID>>>(A);
    k_sq<<<HID, HID>>>(1);
    k_sq<<<HID, HID>>>(0);
    k_sq<<<HID, HID>>>(1);
    k_sq<<<HID, HID>>>(0);
    k_sq<<<HID, HID>>>(1);
    k_sq<<<HID, HID>>>(0);
    k_sq<<<HID, HID>>>(1);            // C = B^128 in g_BB
    k_power<<<1, HID>>>();
    k_prep<<<HID, HID>>>(A, WB, WC);
    k_uproj<<<NROWS/32, 256>>>(x);
    k_rec<<<CHUNKS*(BATCH/NB), 256, REC_SMEM>>>();
    k_yproj<<<NROWS/32, 256>>>(y);
}

// round 15
// speedup vs baseline: 3.4594x; 1.5659x over previous
#include <cuda_runtime.h>
#include <cuda_bf16.h>
#include <math.h>
#include <stdint.h>

#define HID    256
#define CIN    128
#define COUT   128
#define BATCH  32
#define SEQ    4096
#define NROWS  (BATCH*SEQ)
#define CHUNKS 32
#define CHUNK_LEN (SEQ/CHUNKS)   /* 128 */
#define WARM   128
#define PITERS 8
#define NB     8                 /* batches per rec CTA */

/* ---- k_rec SMEM word layout (R12-proven) ---- */
#define A1_WORDS 32768                /* [ks][m][8] interleaved k-pairs: 128KB */
#define HT_PITCH 264                  /* words per n-row, packed (h0|h1)      */
#define HT_BUF   (8*HT_PITCH)         /* 2112 words per buffer                */
#define HT_OFF   A1_WORDS
#define SM_WORDS (A1_WORDS + 2*HT_BUF)
#define REC_SMEM (SM_WORDS*4)         /* 147968 bytes */

/* ---- projection kernels ---- */
#define UP_PITCH 136                  /* K=128 packed words + 8 pad */
#define US_X     0                    /* x tile: 64*136 = 8704 words */
#define US_W     8704                 /* W tile: 128*136 = 17408 words */
#define UP_SMEM  ((8704+17408)*4)     /* 104448 B */
#define YP_PITCH 264                  /* K=256 packed words + 8 pad */
#define YS_H     0                    /* hs tile: 64*264 = 16896 words */
#define YS_W     16896                /* W tile: 128*264 = 33792 words */
#define YP_SMEM  ((16896+33792)*4)    /* 202752 B */

// ---------------- device scratch ------------------------------------------
__device__ float g_BA[HID*HID];
__device__ float g_BB[HID*HID];
__device__ float g_scale;
__device__ __align__(16) __nv_bfloat16 g_A0[HID*HID];  // bf16(A_norm), row-major
__device__ __align__(16) __nv_bfloat16 g_A1[HID*HID];  // bf16(A_norm - A0)
__device__ __align__(16) uint32_t g_WBP[HID*CIN];      // packed split W_B [j][k]
__device__ __align__(16) uint32_t g_WCP[COUT*HID];     // packed split W_C [j][k]
__device__ float    g_u [(size_t)NROWS*HID];           // [t][b][h] fp32
__device__ uint32_t g_hs[(size_t)NROWS*HID];           // [t][b][h] packed (h0|h1)

// ---------------- helpers --------------------------------------------------
__device__ __forceinline__ void mma_bf16(float c[4], const uint32_t a[4],
                                         uint32_t b0, uint32_t b1) {
    asm volatile(
        "mma.sync.aligned.m16n8k16.row.col.f32.bf16.bf16.f32 "
        "{%0,%1,%2,%3}, {%4,%5,%6,%7}, {%8,%9}, {%0,%1,%2,%3};\n"
        : "+f"(c[0]), "+f"(c[1]), "+f"(c[2]), "+f"(c[3])
        : "r"(a[0]), "r"(a[1]), "r"(a[2]), "r"(a[3]), "r"(b0), "r"(b1));
}
__device__ __forceinline__ uint32_t pack_split(float v) {
    __nv_bfloat16 b0 = __float2bfloat16(v);
    __nv_bfloat16 b1 = __float2bfloat16(v - __bfloat162float(b0));
    return (uint32_t)__bfloat16_as_ushort(b0) | ((uint32_t)__bfloat16_as_ushort(b1) << 16);
}

// ---------------- 1) B = A^T A --------------------------------------------
__global__ void k_ata(const float* __restrict__ A) {
    __shared__ float col[HID];
    int i = blockIdx.x, j = threadIdx.x;
    col[j] = A[j*HID + i];
    __syncthreads();
    float a0=0.f,a1=0.f,a2=0.f,a3=0.f;
    #pragma unroll 16
    for (int k = 0; k < HID; k += 4) {
        a0 = fmaf(col[k+0], A[(k+0)*HID + j], a0);
        a1 = fmaf(col[k+1], A[(k+1)*HID + j], a1);
        a2 = fmaf(col[k+2], A[(k+2)*HID + j], a2);
        a3 = fmaf(col[k+3], A[(k+3)*HID + j], a3);
    }
    g_BA[i*HID + j] = (a0+a1)+(a2+a3);
}

// ---------------- 2) B <- B@B (7x => B^128) -------------------------------
__global__ void k_sq(int srcA) {
    const float* __restrict__ Bin = srcA ? g_BA : g_BB;
    float* __restrict__ Bout      = srcA ? g_BB : g_BA;
    __shared__ float row[HID];
    int i = blockIdx.x, j = threadIdx.x;
    row[j] = Bin[i*HID + j];
    __syncthreads();
    float a0=0.f,a1=0.f,a2=0.f,a3=0.f;
    #pragma unroll 16
    for (int k = 0; k < HID; k += 4) {
        a0 = fmaf(row[k+0], Bin[(k+0)*HID + j], a0);
        a1 = fmaf(row[k+1], Bin[(k+1)*HID + j], a1);
        a2 = fmaf(row[k+2], Bin[(k+2)*HID + j], a2);
        a3 = fmaf(row[k+3], Bin[(k+3)*HID + j], a3);
    }
    Bout[i*HID + j] = (a0+a1)+(a2+a3);
}

// ---------------- 3) power iteration on C = B^128 -------------------------
__device__ float red_sum(float v, float* red, int tid) {
    red[tid] = v; __syncthreads();
    for (int s = 128; s > 0; s >>= 1) { if (tid < s) red[tid] += red[tid+s]; __syncthreads(); }
    float r = red[0]; __syncthreads(); return r;
}
__device__ float red_max(float v, float* red, int tid) {
    red[tid] = v; __syncthreads();
    for (int s = 128; s > 0; s >>= 1) { if (tid < s) red[tid] = fmaxf(red[tid], red[tid+s]); __syncthreads(); }
    float r = red[0]; __syncthreads(); return r;
}
__global__ void k_power() {
    __shared__ float v[HID];
    __shared__ float red[HID];
    int tid = threadIdx.x;
    const float* __restrict__ C = g_BB;
    v[tid] = 1.0f;
    __syncthreads();
    float w = 0.f;
    for (int it = 0; it < PITERS; ++it) {
        float a0=0.f,a1=0.f,a2=0.f,a3=0.f;
        #pragma unroll 8
        for (int k = 0; k < HID; k += 4) {
            a0 = fmaf(C[(k+0)*HID + tid], v[k+0], a0);
            a1 = fmaf(C[(k+1)*HID + tid], v[k+1], a1);
            a2 = fmaf(C[(k+2)*HID + tid], v[k+2], a2);
            a3 = fmaf(C[(k+3)*HID + tid], v[k+3], a3);
        }
        w = (a0+a1)+(a2+a3);
        float m = red_max(fabsf(w), red, tid);
        v[tid] = w * (1.0f/m);
        __syncthreads();
    }
    {
        float a0=0.f,a1=0.f,a2=0.f,a3=0.f;
        #pragma unroll 8
        for (int k = 0; k < HID; k += 4) {
            a0 = fmaf(C[(k+0)*HID + tid], v[k+0], a0);
            a1 = fmaf(C[(k+1)*HID + tid], v[k+1], a1);
            a2 = fmaf(C[(k+2)*HID + tid], v[k+2], a2);
            a3 = fmaf(C[(k+3)*HID + tid], v[k+3], a3);
        }
        w = (a0+a1)+(a2+a3);
    }
    float num = red_sum(v[tid]*w,      red, tid);
    float den = red_sum(v[tid]*v[tid], red, tid);
    if (tid == 0) {
        double mu = (double)num / (double)den;       // ~ sigma^256
        double sigma = exp(log(mu) / 256.0);
        g_scale = (float)(1.0 / (sigma + 1e-5));
    }
}

// ---------------- 4) prep: A0/A1 split, packed W_B / W_C -------------------
__global__ void k_prep(const float* __restrict__ A,
                       const float* __restrict__ WB,
                       const float* __restrict__ WC) {
    int bi = blockIdx.x, tj = threadIdx.x;       // 256 x 256
    float s = g_scale;
    float an = A[bi*HID + tj] * s;
    __nv_bfloat16 a0 = __float2bfloat16(an);
    g_A0[bi*HID + tj] = a0;
    g_A1[bi*HID + tj] = __float2bfloat16(an - __bfloat162float(a0));
    if (tj < CIN)  g_WBP[bi*CIN + tj] = pack_split(WB[bi*CIN + tj]);   // [j<256][k<128]
    if (bi < COUT) g_WCP[bi*HID + tj] = pack_split(WC[bi*HID + tj]);   // [j<128][k<256]
}

// ---------------- 5) u = x @ W_B^T on HMMA (writes [t][b][h] fp32) --------
// grid (2048, 2): 64 rows x 128 cols per CTA. 8 warps = 4m x 2n.
__global__ void __launch_bounds__(256,1) k_uprojT(const float* __restrict__ x) {
    extern __shared__ uint32_t us[];
    const int tid = threadIdx.x, w = tid >> 5, l = tid & 31, g = l >> 2, tg = l & 3;
    const int wm = w >> 1, wn = w & 1;
    const int rbase = blockIdx.x * 64;
    const int ncta  = blockIdx.y * 128;

    // stage x tile (convert+split+pack)
    #pragma unroll
    for (int it = 0; it < 8; ++it) {
        int p = tid + it*256;                    // uint4 idx: row=p>>5, c4=(p&31)*4
        int row = p >> 5, c4 = (p & 31) * 4;
        float4 v = *(const float4*)(x + (size_t)(rbase+row)*CIN + c4);
        uint4 pw = make_uint4(pack_split(v.x), pack_split(v.y), pack_split(v.z), pack_split(v.w));
        *(uint4*)(us + US_X + row*UP_PITCH + c4) = pw;
    }
    // stage W_B rows [ncta, ncta+128)
    #pragma unroll
    for (int it = 0; it < 16; ++it) {
        int p = tid + it*256; int jl = p >> 5, c4 = (p & 31) * 4;
        uint4 v = *(const uint4*)(g_WBP + (size_t)(ncta+jl)*CIN + c4);
        *(uint4*)(us + US_W + jl*UP_PITCH + c4) = v;
    }
    __syncthreads();

    float acc[8][4];
    #pragma unroll
    for (int nt = 0; nt < 8; ++nt)
        #pragma unroll
        for (int q = 0; q < 4; ++q) acc[nt][q] = 0.f;

    const int mrow = wm * 16;
    #pragma unroll 2
    for (int ks = 0; ks < 8; ++ks) {
        const uint32_t* xr = us + US_X + (mrow+g)*UP_PITCH + 16*ks + 2*tg;
        uint2 a0w = *(const uint2*)xr;
        uint2 a1w = *(const uint2*)(xr + 8*UP_PITCH);
        uint2 a2w = *(const uint2*)(xr + 8);
        uint2 a3w = *(const uint2*)(xr + 8*UP_PITCH + 8);
        uint32_t x0f[4] = { __byte_perm(a0w.x,a0w.y,0x5410), __byte_perm(a1w.x,a1w.y,0x5410),
                            __byte_perm(a2w.x,a2w.y,0x5410), __byte_perm(a3w.x,a3w.y,0x5410) };
        uint32_t x1f[4] = { __byte_perm(a0w.x,a0w.y,0x7632), __byte_perm(a1w.x,a1w.y,0x7632),
                            __byte_perm(a2w.x,a2w.y,0x7632), __byte_perm(a3w.x,a3w.y,0x7632) };
        #pragma unroll
        for (int nt = 0; nt < 8; ++nt) {
            const uint32_t* wr = us + US_W + (wn*64 + nt*8 + g)*UP_PITCH + 16*ks + 2*tg;
            uint2 wA = *(const uint2*)wr;
            uint2 wB = *(const uint2*)(wr + 8);
            uint32_t w00 = __byte_perm(wA.x,wA.y,0x5410), w01 = __byte_perm(wB.x,wB.y,0x5410);
            uint32_t w10 = __byte_perm(wA.x,wA.y,0x7632), w11 = __byte_perm(wB.x,wB.y,0x7632);
            mma_bf16(acc[nt], x0f, w00, w01);   // x0.w0
            mma_bf16(acc[nt], x1f, w00, w01);   // x1.w0
            mma_bf16(acc[nt], x0f, w10, w11);   // x0.w1
        }
    }
    #pragma unroll
    for (int nt = 0; nt < 8; ++nt)
        #pragma unroll
        for (int q = 0; q < 4; ++q) {
            int grow = rbase + mrow + g + ((q>>1)<<3);
            int b = grow >> 12, t = grow & 4095;
            int col = ncta + wn*64 + nt*8 + 2*tg + (q&1);
            g_u[((size_t)t*BATCH + b)*HID + col] = acc[nt][q];
        }
}

// ---------------- 6) recurrence on mma.sync bf16 (R12-proven loop) --------
__global__ void __launch_bounds__(256,1) k_rec() {
    extern __shared__ uint32_t sw[];
    const int tid = threadIdx.x;
    const int w = tid >> 5, l = tid & 31, g = l >> 2, tg = l & 3;
    const int wb = w * 32;
    const int chunk = blockIdx.x >> 2, bbase = (blockIdx.x & 3) * NB;

    // A1 -> SMEM [ks][m][8], pairs interleaved [c0,c4,c1,c5,c2,c6,c3,c7]
    {
        const uint32_t* A1w = (const uint32_t*)g_A1;     // word = m*128 + kpair
        for (int p = tid; p < HID*HID/2; p += 256) {
            int m = p >> 7, kp = p & 127;
            int ks = kp >> 3, c = kp & 7;
            int pos = (c < 4) ? 2*c : 2*(c-4)+1;
            sw[ks*2048 + m*8 + pos] = A1w[p];
        }
    }
    for (int p = tid; p < 2*HT_BUF; p += 256) sw[HT_OFF + p] = 0;

    uint32_t a0f[2][16][4];
    {
        const uint32_t* A0w = (const uint32_t*)g_A0;
        #pragma unroll
        for (int mt = 0; mt < 2; ++mt) {
            int mr = wb + mt*16 + g;
            #pragma unroll
            for (int ks = 0; ks < 16; ++ks) {
                int base = 8*ks + tg;
                a0f[mt][ks][0] = A0w[(size_t)mr*128 + base];
                a0f[mt][ks][1] = A0w[(size_t)(mr+8)*128 + base];
                a0f[mt][ks][2] = A0w[(size_t)mr*128 + base + 4];
                a0f[mt][ks][3] = A0w[(size_t)(mr+8)*128 + base + 4];
            }
        }
    }
    __syncthreads();

    int t0 = chunk*CHUNK_LEN - WARM; if (t0 < 0) t0 = 0;
    const int t1 = chunk*CHUNK_LEN, tend = t1 + CHUNK_LEN;

    float ur[2][4];
    {
        const float* ub = g_u + ((size_t)t0*BATCH + bbase)*HID;
        #pragma unroll
        for (int mt = 0; mt < 2; ++mt) {
            int m0 = wb + mt*16 + g;
            #pragma unroll
            for (int q = 0; q < 4; ++q)
                ur[mt][q] = ub[(size_t)(2*tg + (q&1))*HID + m0 + ((q>>1)<<3)];
        }
    }

    int par = 0;
    for (int t = t0; t < tend; ++t, par ^= 1) {
        const uint32_t* hb = sw + HT_OFF + par*HT_BUF;
        uint32_t* wbuf     = sw + HT_OFF + (par^1)*HT_BUF;

        float urn[2][4];
        {
            int tn = (t + 1 < tend) ? t + 1 : t;
            const float* ub = g_u + ((size_t)tn*BATCH + bbase)*HID;
            #pragma unroll
            for (int mt = 0; mt < 2; ++mt) {
                int m0 = wb + mt*16 + g;
                #pragma unroll
                for (int q = 0; q < 4; ++q)
                    urn[mt][q] = ub[(size_t)(2*tg + (q&1))*HID + m0 + ((q>>1)<<3)];
            }
        }

        float acc0[2][4] = {{0,0,0,0},{0,0,0,0}};
        float acc1[2][4] = {{0,0,0,0},{0,0,0,0}};
        float acc2[2][4] = {{0,0,0,0},{0,0,0,0}};
        #pragma unroll
        for (int ks = 0; ks < 16; ++ks) {
            const uint32_t* hrow = hb + g*HT_PITCH + 16*ks + 2*tg;
            uint2 hA = *(const uint2*)hrow;
            uint2 hB = *(const uint2*)(hrow + 8);
            uint32_t b00 = __byte_perm(hA.x, hA.y, 0x5410);
            uint32_t b10 = __byte_perm(hA.x, hA.y, 0x7632);
            uint32_t b01 = __byte_perm(hB.x, hB.y, 0x5410);
            uint32_t b11 = __byte_perm(hB.x, hB.y, 0x7632);
            const uint32_t* pan = sw + ks*2048;
            #pragma unroll
            for (int mt = 0; mt < 2; ++mt) {
                int mr = wb + mt*16 + g;
                uint2 rlo = *(const uint2*)(pan + mr*8 + 2*tg);
                uint2 rhi = *(const uint2*)(pan + (mr+8)*8 + 2*tg);
                uint32_t a1f[4] = {rlo.x, rhi.x, rlo.y, rhi.y};
                mma_bf16(acc0[mt], a0f[mt][ks], b00, b01);
                mma_bf16(acc1[mt], a0f[mt][ks], b10, b11);
                mma_bf16(acc2[mt], a1f,         b00, b01);
            }
        }

        {
            bool emit = (t >= t1);
            uint32_t* hsb = g_hs + ((size_t)t*BATCH + bbase)*HID;
            #pragma unroll
            for (int mt = 0; mt < 2; ++mt) {
                #pragma unroll
                for (int q = 0; q < 4; ++q) {
                    int m = wb + mt*16 + g + ((q>>1)<<3);
                    int n = 2*tg + (q&1);
                    float hv = fmaxf(acc0[mt][q] + acc1[mt][q] + acc2[mt][q] + ur[mt][q], 0.f);
                    __nv_bfloat16 h0 = __float2bfloat16(hv);
                    __nv_bfloat16 h1 = __float2bfloat16(hv - __bfloat162float(h0));
                    uint32_t word = (uint32_t)__bfloat16_as_ushort(h0)
                                  | ((uint32_t)__bfloat16_as_ushort(h1) << 16);
                    wbuf[n*HT_PITCH + m] = word;
                    if (emit) hsb[(size_t)n*HID + m] = word;
                }
            }
        }
        #pragma unroll
        for (int mt = 0; mt < 2; ++mt)
            #pragma unroll
            for (int q = 0; q < 4; ++q) ur[mt][q] = urn[mt][q];
        __syncthreads();
    }
}

// ---------------- 7) y = hs @ W_C^T on HMMA (reads packed hs) -------------
// grid 2048: 64 rows x 128 cols per CTA. 8 warps = 4m x 2n.
__global__ void __launch_bounds__(256,1) k_yprojT(float* __restrict__ y) {
    extern __shared__ uint32_t ys[];
    const int tid = threadIdx.x, w = tid >> 5, l = tid & 31, g = l >> 2, tg = l & 3;
    const int wm = w >> 1, wn = w & 1;
    const int rbase = blockIdx.x * 64;

    // stage hs tile (already packed)
    #pragma unroll
    for (int it = 0; it < 16; ++it) {
        int p = tid + it*256; int row = p >> 6, c4 = (p & 63) * 4;
        uint4 v = *(const uint4*)(g_hs + (size_t)(rbase+row)*HID + c4);
        *(uint4*)(ys + YS_H + row*YP_PITCH + c4) = v;
    }
    // stage W_C (all 128 rows)
    #pragma unroll
    for (int it = 0; it < 32; ++it) {
        int p = tid + it*256; int jl = p >> 6, c4 = (p & 63) * 4;
        uint4 v = *(const uint4*)(g_WCP + (size_t)jl*HID + c4);
        *(uint4*)(ys + YS_W + jl*YP_PITCH + c4) = v;
    }
    __syncthreads();

    float acc[8][4];
    #pragma unroll
    for (int nt = 0; nt < 8; ++nt)
        #pragma unroll
        for (int q = 0; q < 4; ++q) acc[nt][q] = 0.f;

    const int mrow = wm * 16;
    #pragma unroll 2
    for (int ks = 0; ks < 16; ++ks) {
        const uint32_t* hr = ys + YS_H + (mrow+g)*YP_PITCH + 16*ks + 2*tg;
        uint2 a0w = *(const uint2*)hr;
        uint2 a1w = *(const uint2*)(hr + 8*YP_PITCH);
        uint2 a2w = *(const uint2*)(hr + 8);
        uint2 a3w = *(const uint2*)(hr + 8*YP_PITCH + 8);
        uint32_t h0f[4] = { __byte_perm(a0w.x,a0w.y,0x5410), __byte_perm(a1w.x,a1w.y,0x5410),
                            __byte_perm(a2w.x,a2w.y,0x5410), __byte_perm(a3w.x,a3w.y,0x5410) };
        uint32_t h1f[4] = { __byte_perm(a0w.x,a0w.y,0x7632), __byte_perm(a1w.x,a1w.y,0x7632),
                            __byte_perm(a2w.x,a2w.y,0x7632), __byte_perm(a3w.x,a3w.y,0x7632) };
        #pragma unroll
        for (int nt = 0; nt < 8; ++nt) {
            const uint32_t* wr = ys + YS_W + (wn*64 + nt*8 + g)*YP_PITCH + 16*ks + 2*tg;
            uint2 wA = *(const uint2*)wr;
            uint2 wB = *(const uint2*)(wr + 8);
            uint32_t w00 = __byte_perm(wA.x,wA.y,0x5410), w01 = __byte_perm(wB.x,wB.y,0x5410);
            uint32_t w10 = __byte_perm(wA.x,wA.y,0x7632), w11 = __byte_perm(wB.x,wB.y,0x7632);
            mma_bf16(acc[nt], h0f, w00, w01);   // h0.w0
            mma_bf16(acc[nt], h1f, w00, w01);   // h1.w0
            mma_bf16(acc[nt], h0f, w10, w11);   // h0.w1
        }
    }
    #pragma unroll
    for (int nt = 0; nt < 8; ++nt)
        #pragma unroll
        for (int q = 0; q < 4; ++q) {
            int grow = rbase + mrow + g + ((q>>1)<<3);   // row = t*32 + b
            int t = grow >> 5, b = grow & 31;
            int col = wn*64 + nt*8 + 2*tg + (q&1);
            y[((size_t)b*SEQ + t)*COUT + col] = acc[nt][q];
        }
}

// ---------------- launch ---------------------------------------------------
extern "C" void kernel_launch(void* const* d_in, const int* in_sizes, int n_in,
                              void* d_out, int out_size) {
    const float* x  = (const float*)d_in[0];
    const float* A  = (const float*)d_in[1];
    const float* WB = (const float*)d_in[2];
    const float* WC = (const float*)d_in[3];
    float* y = (float*)d_out;

    cudaFuncSetAttribute(k_rec,    cudaFuncAttributeMaxDynamicSharedMemorySize, REC_SMEM);
    cudaFuncSetAttribute(k_uprojT, cudaFuncAttributeMaxDynamicSharedMemorySize, UP_SMEM);
    cudaFuncSetAttribute(k_yprojT, cudaFuncAttributeMaxDynamicSharedMemorySize, YP_SMEM);

    k_ata<<<HID, HID>>>(A);
    k_sq<<<HID, HID>>>(1);
    k_sq<<<HID, HID>>>(0);
    k_sq<<<HID, HID>>>(1);
    k_sq<<<HID, HID>>>(0);
    k_sq<<<HID, HID>>>(1);
    k_sq<<<HID, HID>>>(0);
    k_sq<<<HID, HID>>>(1);            // C = B^128 in g_BB
    k_power<<<1, HID>>>();
    k_prep<<<HID, HID>>>(A, WB, WC);
    k_uprojT<<<dim3(NROWS/64, 2), 256, UP_SMEM>>>(x);
    k_rec<<<CHUNKS*(BATCH/NB), 256, REC_SMEM>>>();
    k_yprojT<<<NROWS/64, 256, YP_SMEM>>>(y);
}

// round 16
// speedup vs baseline: 3.7278x; 1.0776x over previous
#include <cuda_runtime.h>
#include <cuda_bf16.h>
#include <math.h>
#include <stdint.h>

#define HID    256
#define CIN    128
#define COUT   128
#define BATCH  32
#define SEQ    4096
#define NROWS  (BATCH*SEQ)
#define CHUNKS 32
#define CHUNK_LEN (SEQ/CHUNKS)   /* 128 */
#define WARM   96
#define FULLWARM 64               /* full-precision warm steps before emit */
#define PITERS 8
#define NB     8                 /* batches per rec CTA */

/* ---- k_rec SMEM word layout (R12-proven) ---- */
#define A1_WORDS 32768                /* [ks][m][8] interleaved k-pairs: 128KB */
#define HT_PITCH 264                  /* words per n-row, packed (h0|h1)      */
#define HT_BUF   (8*HT_PITCH)         /* 2112 words per buffer                */
#define HT_OFF   A1_WORDS
#define SM_WORDS (A1_WORDS + 2*HT_BUF)
#define REC_SMEM (SM_WORDS*4)         /* 147968 bytes */

/* ---- projection kernels ---- */
#define UP_PITCH 136
#define US_X     0
#define US_W     8704
#define UP_SMEM  ((8704+17408)*4)     /* 104448 B */
#define YP_PITCH 264
#define YS_H     0
#define YS_W     16896
#define YP_SMEM  ((16896+33792)*4)    /* 202752 B */

// ---------------- device scratch ------------------------------------------
__device__ float g_BA[HID*HID];
__device__ float g_BB[HID*HID];
__device__ float g_scale;
__device__ __align__(16) __nv_bfloat16 g_A0[HID*HID];
__device__ __align__(16) __nv_bfloat16 g_A1[HID*HID];
__device__ __align__(16) uint32_t g_WBP[HID*CIN];
__device__ __align__(16) uint32_t g_WCP[COUT*HID];
__device__ float    g_u [(size_t)NROWS*HID];           // [t][b][h] fp32
__device__ uint32_t g_hs[(size_t)NROWS*HID];           // [t][b][h] packed (h0|h1)

// ---------------- helpers --------------------------------------------------
__device__ __forceinline__ void mma_bf16(float c[4], const uint32_t a[4],
                                         uint32_t b0, uint32_t b1) {
    asm volatile(
        "mma.sync.aligned.m16n8k16.row.col.f32.bf16.bf16.f32 "
        "{%0,%1,%2,%3}, {%4,%5,%6,%7}, {%8,%9}, {%0,%1,%2,%3};\n"
        : "+f"(c[0]), "+f"(c[1]), "+f"(c[2]), "+f"(c[3])
        : "r"(a[0]), "r"(a[1]), "r"(a[2]), "r"(a[3]), "r"(b0), "r"(b1));
}
__device__ __forceinline__ uint32_t pack_split(float v) {
    __nv_bfloat16 b0 = __float2bfloat16(v);
    __nv_bfloat16 b1 = __float2bfloat16(v - __bfloat162float(b0));
    return (uint32_t)__bfloat16_as_ushort(b0) | ((uint32_t)__bfloat16_as_ushort(b1) << 16);
}

// ---------------- 1) B = A^T A --------------------------------------------
__global__ void k_ata(const float* __restrict__ A) {
    __shared__ float col[HID];
    int i = blockIdx.x, j = threadIdx.x;
    col[j] = A[j*HID + i];
    __syncthreads();
    float a0=0.f,a1=0.f,a2=0.f,a3=0.f;
    #pragma unroll 16
    for (int k = 0; k < HID; k += 4) {
        a0 = fmaf(col[k+0], A[(k+0)*HID + j], a0);
        a1 = fmaf(col[k+1], A[(k+1)*HID + j], a1);
        a2 = fmaf(col[k+2], A[(k+2)*HID + j], a2);
        a3 = fmaf(col[k+3], A[(k+3)*HID + j], a3);
    }
    g_BA[i*HID + j] = (a0+a1)+(a2+a3);
}

// ---------------- 2) B <- B@B (7x => B^128) -------------------------------
__global__ void k_sq(int srcA) {
    const float* __restrict__ Bin = srcA ? g_BA : g_BB;
    float* __restrict__ Bout      = srcA ? g_BB : g_BA;
    __shared__ float row[HID];
    int i = blockIdx.x, j = threadIdx.x;
    row[j] = Bin[i*HID + j];
    __syncthreads();
    float a0=0.f,a1=0.f,a2=0.f,a3=0.f;
    #pragma unroll 16
    for (int k = 0; k < HID; k += 4) {
        a0 = fmaf(row[k+0], Bin[(k+0)*HID + j], a0);
        a1 = fmaf(row[k+1], Bin[(k+1)*HID + j], a1);
        a2 = fmaf(row[k+2], Bin[(k+2)*HID + j], a2);
        a3 = fmaf(row[k+3], Bin[(k+3)*HID + j], a3);
    }
    Bout[i*HID + j] = (a0+a1)+(a2+a3);
}

// ---------------- 3) power iteration on C = B^128 -------------------------
__device__ float red_sum(float v, float* red, int tid) {
    red[tid] = v; __syncthreads();
    for (int s = 128; s > 0; s >>= 1) { if (tid < s) red[tid] += red[tid+s]; __syncthreads(); }
    float r = red[0]; __syncthreads(); return r;
}
__device__ float red_max(float v, float* red, int tid) {
    red[tid] = v; __syncthreads();
    for (int s = 128; s > 0; s >>= 1) { if (tid < s) red[tid] = fmaxf(red[tid], red[tid+s]); __syncthreads(); }
    float r = red[0]; __syncthreads(); return r;
}
__global__ void k_power() {
    __shared__ float v[HID];
    __shared__ float red[HID];
    int tid = threadIdx.x;
    const float* __restrict__ C = g_BB;
    v[tid] = 1.0f;
    __syncthreads();
    float w = 0.f;
    for (int it = 0; it < PITERS; ++it) {
        float a0=0.f,a1=0.f,a2=0.f,a3=0.f;
        #pragma unroll 8
        for (int k = 0; k < HID; k += 4) {
            a0 = fmaf(C[(k+0)*HID + tid], v[k+0], a0);
            a1 = fmaf(C[(k+1)*HID + tid], v[k+1], a1);
            a2 = fmaf(C[(k+2)*HID + tid], v[k+2], a2);
            a3 = fmaf(C[(k+3)*HID + tid], v[k+3], a3);
        }
        w = (a0+a1)+(a2+a3);
        float m = red_max(fabsf(w), red, tid);
        v[tid] = w * (1.0f/m);
        __syncthreads();
    }
    {
        float a0=0.f,a1=0.f,a2=0.f,a3=0.f;
        #pragma unroll 8
        for (int k = 0; k < HID; k += 4) {
            a0 = fmaf(C[(k+0)*HID + tid], v[k+0], a0);
            a1 = fmaf(C[(k+1)*HID + tid], v[k+1], a1);
            a2 = fmaf(C[(k+2)*HID + tid], v[k+2], a2);
            a3 = fmaf(C[(k+3)*HID + tid], v[k+3], a3);
        }
        w = (a0+a1)+(a2+a3);
    }
    float num = red_sum(v[tid]*w,      red, tid);
    float den = red_sum(v[tid]*v[tid], red, tid);
    if (tid == 0) {
        double mu = (double)num / (double)den;       // ~ sigma^256
        double sigma = exp(log(mu) / 256.0);
        g_scale = (float)(1.0 / (sigma + 1e-5));
    }
}

// ---------------- 4a) prep A0/A1 (needs g_scale) ---------------------------
__global__ void k_prep(const float* __restrict__ A) {
    int bi = blockIdx.x, tj = threadIdx.x;       // 256 x 256
    float an = A[bi*HID + tj] * g_scale;
    __nv_bfloat16 a0 = __float2bfloat16(an);
    g_A0[bi*HID + tj] = a0;
    g_A1[bi*HID + tj] = __float2bfloat16(an - __bfloat162float(a0));
}

// ---------------- 4b) pack W_B / W_C (scale-independent) -------------------
__global__ void k_packw(const float* __restrict__ WB, const float* __restrict__ WC) {
    int bi = blockIdx.x, tj = threadIdx.x;       // 256 x 256
    if (tj < CIN)  g_WBP[bi*CIN + tj] = pack_split(WB[bi*CIN + tj]);
    if (bi < COUT) g_WCP[bi*HID + tj] = pack_split(WC[bi*HID + tj]);
}

// ---------------- 5) u = x @ W_B^T on HMMA (writes [t][b][h] fp32) --------
__global__ void __launch_bounds__(256,1) k_uprojT(const float* __restrict__ x) {
    extern __shared__ uint32_t us[];
    const int tid = threadIdx.x, w = tid >> 5, l = tid & 31, g = l >> 2, tg = l & 3;
    const int wm = w >> 1, wn = w & 1;
    const int rbase = blockIdx.x * 64;
    const int ncta  = blockIdx.y * 128;

    #pragma unroll
    for (int it = 0; it < 8; ++it) {
        int p = tid + it*256;
        int row = p >> 5, c4 = (p & 31) * 4;
        float4 v = *(const float4*)(x + (size_t)(rbase+row)*CIN + c4);
        uint4 pw = make_uint4(pack_split(v.x), pack_split(v.y), pack_split(v.z), pack_split(v.w));
        *(uint4*)(us + US_X + row*UP_PITCH + c4) = pw;
    }
    #pragma unroll
    for (int it = 0; it < 16; ++it) {
        int p = tid + it*256; int jl = p >> 5, c4 = (p & 31) * 4;
        uint4 v = *(const uint4*)(g_WBP + (size_t)(ncta+jl)*CIN + c4);
        *(uint4*)(us + US_W + jl*UP_PITCH + c4) = v;
    }
    __syncthreads();

    float acc[8][4];
    #pragma unroll
    for (int nt = 0; nt < 8; ++nt)
        #pragma unroll
        for (int q = 0; q < 4; ++q) acc[nt][q] = 0.f;

    const int mrow = wm * 16;
    #pragma unroll 2
    for (int ks = 0; ks < 8; ++ks) {
        const uint32_t* xr = us + US_X + (mrow+g)*UP_PITCH + 16*ks + 2*tg;
        uint2 a0w = *(const uint2*)xr;
        uint2 a1w = *(const uint2*)(xr + 8*UP_PITCH);
        uint2 a2w = *(const uint2*)(xr + 8);
        uint2 a3w = *(const uint2*)(xr + 8*UP_PITCH + 8);
        uint32_t x0f[4] = { __byte_perm(a0w.x,a0w.y,0x5410), __byte_perm(a1w.x,a1w.y,0x5410),
                            __byte_perm(a2w.x,a2w.y,0x5410), __byte_perm(a3w.x,a3w.y,0x5410) };
        uint32_t x1f[4] = { __byte_perm(a0w.x,a0w.y,0x7632), __byte_perm(a1w.x,a1w.y,0x7632),
                            __byte_perm(a2w.x,a2w.y,0x7632), __byte_perm(a3w.x,a3w.y,0x7632) };
        #pragma unroll
        for (int nt = 0; nt < 8; ++nt) {
            const uint32_t* wr = us + US_W + (wn*64 + nt*8 + g)*UP_PITCH + 16*ks + 2*tg;
            uint2 wA = *(const uint2*)wr;
            uint2 wB = *(const uint2*)(wr + 8);
            uint32_t w00 = __byte_perm(wA.x,wA.y,0x5410), w01 = __byte_perm(wB.x,wB.y,0x5410);
            uint32_t w10 = __byte_perm(wA.x,wA.y,0x7632), w11 = __byte_perm(wB.x,wB.y,0x7632);
            mma_bf16(acc[nt], x0f, w00, w01);
            mma_bf16(acc[nt], x1f, w00, w01);
            mma_bf16(acc[nt], x0f, w10, w11);
        }
    }
    #pragma unroll
    for (int nt = 0; nt < 8; ++nt)
        #pragma unroll
        for (int q = 0; q < 4; ++q) {
            int grow = rbase + mrow + g + ((q>>1)<<3);
            int b = grow >> 12, t = grow & 4095;
            int col = ncta + wn*64 + nt*8 + 2*tg + (q&1);
            g_u[((size_t)t*BATCH + b)*HID + col] = acc[nt][q];
        }
}

// ---------------- 6) recurrence on mma.sync bf16 ---------------------------
// Light steps (first WARM-FULLWARM warm steps): skip A1 pass (2-pass).
__global__ void __launch_bounds__(256,1) k_rec() {
    extern __shared__ uint32_t sw[];
    const int tid = threadIdx.x;
    const int w = tid >> 5, l = tid & 31, g = l >> 2, tg = l & 3;
    const int wb = w * 32;
    const int chunk = blockIdx.x >> 2, bbase = (blockIdx.x & 3) * NB;

    {
        const uint32_t* A1w = (const uint32_t*)g_A1;
        for (int p = tid; p < HID*HID/2; p += 256) {
            int m = p >> 7, kp = p & 127;
            int ks = kp >> 3, c = kp & 7;
            int pos = (c < 4) ? 2*c : 2*(c-4)+1;
            sw[ks*2048 + m*8 + pos] = A1w[p];
        }
    }
    for (int p = tid; p < 2*HT_BUF; p += 256) sw[HT_OFF + p] = 0;

    uint32_t a0f[2][16][4];
    {
        const uint32_t* A0w = (const uint32_t*)g_A0;
        #pragma unroll
        for (int mt = 0; mt < 2; ++mt) {
            int mr = wb + mt*16 + g;
            #pragma unroll
            for (int ks = 0; ks < 16; ++ks) {
                int base = 8*ks + tg;
                a0f[mt][ks][0] = A0w[(size_t)mr*128 + base];
                a0f[mt][ks][1] = A0w[(size_t)(mr+8)*128 + base];
                a0f[mt][ks][2] = A0w[(size_t)mr*128 + base + 4];
                a0f[mt][ks][3] = A0w[(size_t)(mr+8)*128 + base + 4];
            }
        }
    }
    __syncthreads();

    int t0 = chunk*CHUNK_LEN - WARM; if (t0 < 0) t0 = 0;
    const int t1 = chunk*CHUNK_LEN, tend = t1 + CHUNK_LEN;
    int lend = t1 - FULLWARM; if (lend < t0) lend = t0;

    float ur[2][4];
    {
        const float* ub = g_u + ((size_t)t0*BATCH + bbase)*HID;
        #pragma unroll
        for (int mt = 0; mt < 2; ++mt) {
            int m0 = wb + mt*16 + g;
            #pragma unroll
            for (int q = 0; q < 4; ++q)
                ur[mt][q] = ub[(size_t)(2*tg + (q&1))*HID + m0 + ((q>>1)<<3)];
        }
    }

    int par = 0;
    auto step = [&](int t, bool light) {
        const uint32_t* hb = sw + HT_OFF + par*HT_BUF;
        uint32_t* wbuf     = sw + HT_OFF + (par^1)*HT_BUF;

        float urn[2][4];
        {
            int tn = (t + 1 < tend) ? t + 1 : t;
            const float* ub = g_u + ((size_t)tn*BATCH + bbase)*HID;
            #pragma unroll
            for (int mt = 0; mt < 2; ++mt) {
                int m0 = wb + mt*16 + g;
                #pragma unroll
                for (int q = 0; q < 4; ++q)
                    urn[mt][q] = ub[(size_t)(2*tg + (q&1))*HID + m0 + ((q>>1)<<3)];
            }
        }

        float acc0[2][4] = {{0,0,0,0},{0,0,0,0}};
        float acc1[2][4] = {{0,0,0,0},{0,0,0,0}};
        float acc2[2][4] = {{0,0,0,0},{0,0,0,0}};
        if (light) {
            #pragma unroll
            for (int ks = 0; ks < 16; ++ks) {
                const uint32_t* hrow = hb + g*HT_PITCH + 16*ks + 2*tg;
                uint2 hA = *(const uint2*)hrow;
                uint2 hB = *(const uint2*)(hrow + 8);
                uint32_t b00 = __byte_perm(hA.x, hA.y, 0x5410);
                uint32_t b10 = __byte_perm(hA.x, hA.y, 0x7632);
                uint32_t b01 = __byte_perm(hB.x, hB.y, 0x5410);
                uint32_t b11 = __byte_perm(hB.x, hB.y, 0x7632);
                #pragma unroll
                for (int mt = 0; mt < 2; ++mt) {
                    mma_bf16(acc0[mt], a0f[mt][ks], b00, b01);
                    mma_bf16(acc1[mt], a0f[mt][ks], b10, b11);
                }
            }
        } else {
            #pragma unroll
            for (int ks = 0; ks < 16; ++ks) {
                const uint32_t* hrow = hb + g*HT_PITCH + 16*ks + 2*tg;
                uint2 hA = *(const uint2*)hrow;
                uint2 hB = *(const uint2*)(hrow + 8);
                uint32_t b00 = __byte_perm(hA.x, hA.y, 0x5410);
                uint32_t b10 = __byte_perm(hA.x, hA.y, 0x7632);
                uint32_t b01 = __byte_perm(hB.x, hB.y, 0x5410);
                uint32_t b11 = __byte_perm(hB.x, hB.y, 0x7632);
                const uint32_t* pan = sw + ks*2048;
                #pragma unroll
                for (int mt = 0; mt < 2; ++mt) {
                    int mr = wb + mt*16 + g;
                    uint2 rlo = *(const uint2*)(pan + mr*8 + 2*tg);
                    uint2 rhi = *(const uint2*)(pan + (mr+8)*8 + 2*tg);
                    uint32_t a1f[4] = {rlo.x, rhi.x, rlo.y, rhi.y};
                    mma_bf16(acc0[mt], a0f[mt][ks], b00, b01);
                    mma_bf16(acc1[mt], a0f[mt][ks], b10, b11);
                    mma_bf16(acc2[mt], a1f,         b00, b01);
                }
            }
        }

        {
            bool emit = (t >= t1);
            uint32_t* hsb = g_hs + ((size_t)t*BATCH + bbase)*HID;
            #pragma unroll
            for (int mt = 0; mt < 2; ++mt) {
                #pragma unroll
                for (int q = 0; q < 4; ++q) {
                    int m = wb + mt*16 + g + ((q>>1)<<3);
                    int n = 2*tg + (q&1);
                    float hv = fmaxf(acc0[mt][q] + acc1[mt][q] + acc2[mt][q] + ur[mt][q], 0.f);
                    __nv_bfloat16 h0 = __float2bfloat16(hv);
                    __nv_bfloat16 h1 = __float2bfloat16(hv - __bfloat162float(h0));
                    uint32_t word = (uint32_t)__bfloat16_as_ushort(h0)
                                  | ((uint32_t)__bfloat16_as_ushort(h1) << 16);
                    wbuf[n*HT_PITCH + m] = word;
                    if (emit) hsb[(size_t)n*HID + m] = word;
                }
            }
        }
        #pragma unroll
        for (int mt = 0; mt < 2; ++mt)
            #pragma unroll
            for (int q = 0; q < 4; ++q) ur[mt][q] = urn[mt][q];
        __syncthreads();
        par ^= 1;
    };

    for (int t = t0; t < lend; ++t) step(t, true);
    for (int t = lend; t < tend; ++t) step(t, false);
}

// ---------------- 7) y = hs @ W_C^T on HMMA (reads packed hs) -------------
__global__ void __launch_bounds__(256,1) k_yprojT(float* __restrict__ y) {
    extern __shared__ uint32_t ys[];
    const int tid = threadIdx.x, w = tid >> 5, l = tid & 31, g = l >> 2, tg = l & 3;
    const int wm = w >> 1, wn = w & 1;
    const int rbase = blockIdx.x * 64;

    #pragma unroll
    for (int it = 0; it < 16; ++it) {
        int p = tid + it*256; int row = p >> 6, c4 = (p & 63) * 4;
        uint4 v = *(const uint4*)(g_hs + (size_t)(rbase+row)*HID + c4);
        *(uint4*)(ys + YS_H + row*YP_PITCH + c4) = v;
    }
    #pragma unroll
    for (int it = 0; it < 32; ++it) {
        int p = tid + it*256; int jl = p >> 6, c4 = (p & 63) * 4;
        uint4 v = *(const uint4*)(g_WCP + (size_t)jl*HID + c4);
        *(uint4*)(ys + YS_W + jl*YP_PITCH + c4) = v;
    }
    __syncthreads();

    float acc[8][4];
    #pragma unroll
    for (int nt = 0; nt < 8; ++nt)
        #pragma unroll
        for (int q = 0; q < 4; ++q) acc[nt][q] = 0.f;

    const int mrow = wm * 16;
    #pragma unroll 2
    for (int ks = 0; ks < 16; ++ks) {
        const uint32_t* hr = ys + YS_H + (mrow+g)*YP_PITCH + 16*ks + 2*tg;
        uint2 a0w = *(const uint2*)hr;
        uint2 a1w = *(const uint2*)(hr + 8*YP_PITCH);
        uint2 a2w = *(const uint2*)(hr + 8);
        uint2 a3w = *(const uint2*)(hr + 8*YP_PITCH + 8);
        uint32_t h0f[4] = { __byte_perm(a0w.x,a0w.y,0x5410), __byte_perm(a1w.x,a1w.y,0x5410),
                            __byte_perm(a2w.x,a2w.y,0x5410), __byte_perm(a3w.x,a3w.y,0x5410) };
        uint32_t h1f[4] = { __byte_perm(a0w.x,a0w.y,0x7632), __byte_perm(a1w.x,a1w.y,0x7632),
                            __byte_perm(a2w.x,a2w.y,0x7632), __byte_perm(a3w.x,a3w.y,0x7632) };
        #pragma unroll
        for (int nt = 0; nt < 8; ++nt) {
            const uint32_t* wr = ys + YS_W + (wn*64 + nt*8 + g)*YP_PITCH + 16*ks + 2*tg;
            uint2 wA = *(const uint2*)wr;
            uint2 wB = *(const uint2*)(wr + 8);
            uint32_t w00 = __byte_perm(wA.x,wA.y,0x5410), w01 = __byte_perm(wB.x,wB.y,0x5410);
            uint32_t w10 = __byte_perm(wA.x,wA.y,0x7632), w11 = __byte_perm(wB.x,wB.y,0x7632);
            mma_bf16(acc[nt], h0f, w00, w01);
            mma_bf16(acc[nt], h1f, w00, w01);
            mma_bf16(acc[nt], h0f, w10, w11);
        }
    }
    #pragma unroll
    for (int nt = 0; nt < 8; ++nt)
        #pragma unroll
        for (int q = 0; q < 4; ++q) {
            int grow = rbase + mrow + g + ((q>>1)<<3);   // row = t*32 + b
            int t = grow >> 5, b = grow & 31;
            int col = wn*64 + nt*8 + 2*tg + (q&1);
            y[((size_t)b*SEQ + t)*COUT + col] = acc[nt][q];
        }
}

// ---------------- launch ---------------------------------------------------
extern "C" void kernel_launch(void* const* d_in, const int* in_sizes, int n_in,
                              void* d_out, int out_size) {
    const float* x  = (const float*)d_in[0];
    const float* A  = (const float*)d_in[1];
    const float* WB = (const float*)d_in[2];
    const float* WC = (const float*)d_in[3];
    float* y = (float*)d_out;

    static cudaStream_t s2 = nullptr;
    static cudaEvent_t eF = nullptr, eJ = nullptr;
    if (s2 == nullptr) {
        cudaStreamCreateWithFlags(&s2, cudaStreamNonBlocking);
        cudaEventCreateWithFlags(&eF, cudaEventDisableTiming);
        cudaEventCreateWithFlags(&eJ, cudaEventDisableTiming);
        cudaFuncSetAttribute(k_rec,    cudaFuncAttributeMaxDynamicSharedMemorySize, REC_SMEM);
        cudaFuncSetAttribute(k_uprojT, cudaFuncAttributeMaxDynamicSharedMemorySize, UP_SMEM);
        cudaFuncSetAttribute(k_yprojT, cudaFuncAttributeMaxDynamicSharedMemorySize, YP_SMEM);
    }

    // fork: u-projection branch (independent of spectral norm)
    cudaEventRecord(eF, 0);
    cudaStreamWaitEvent(s2, eF, 0);
    k_packw<<<HID, HID, 0, s2>>>(WB, WC);
    k_uprojT<<<dim3(NROWS/64, 2), 256, UP_SMEM, s2>>>(x);
    cudaEventRecord(eJ, s2);

    // spectral-norm branch on the main stream
    k_ata<<<HID, HID>>>(A);
    k_sq<<<HID, HID>>>(1);
    k_sq<<<HID, HID>>>(0);
    k_sq<<<HID, HID>>>(1);
    k_sq<<<HID, HID>>>(0);
    k_sq<<<HID, HID>>>(1);
    k_sq<<<HID, HID>>>(0);
    k_sq<<<HID, HID>>>(1);            // C = B^128 in g_BB
    k_power<<<1, HID>>>();
    k_prep<<<HID, HID>>>(A);

    // join, then recurrence + output projection
    cudaStreamWaitEvent(0, eJ, 0);
    k_rec<<<CHUNKS*(BATCH/NB), 256, REC_SMEM>>>();
    k_yprojT<<<NROWS/64, 256, YP_SMEM>>>(y);
}

// round 17
// speedup vs baseline: 4.1969x; 1.1258x over previous
#include <cuda_runtime.h>
#include <cuda_bf16.h>
#include <math.h>
#include <stdint.h>

#define HID    256
#define CIN    128
#define COUT   128
#define BATCH  32
#define SEQ    4096
#define NROWS  (BATCH*SEQ)
#define NCHUNK 37                 /* 37 chunks x 4 batch-groups = 148 CTAs (one wave) */
#define WARM   64
#define FULLWARM 48               /* full-precision warm steps before emit */
#define PITERS 8
#define NB     8                  /* batches per rec CTA */

/* ---- k_rec SMEM word layout (R12-proven) ---- */
#define A1_WORDS 32768                /* [ks][m][8] interleaved k-pairs: 128KB */
#define HT_PITCH 264                  /* words per n-row, packed (h0|h1)      */
#define HT_BUF   (8*HT_PITCH)         /* 2112 words per buffer                */
#define HT_OFF   A1_WORDS
#define SM_WORDS (A1_WORDS + 2*HT_BUF)
#define REC_SMEM (SM_WORDS*4)         /* 147968 bytes */

/* ---- projection kernels ---- */
#define UP_PITCH 136
#define US_X     0
#define US_W     8704
#define UP_SMEM  ((8704+17408)*4)     /* 104448 B */
#define YP_PITCH 264
#define YS_H     0
#define YS_W     16896
#define YP_SMEM  ((16896+33792)*4)    /* 202752 B */

// ---------------- device scratch ------------------------------------------
__device__ float g_BA[HID*HID];
__device__ float g_BB[HID*HID];
__device__ float g_scale;
__device__ __align__(16) __nv_bfloat16 g_A0[HID*HID];
__device__ __align__(16) __nv_bfloat16 g_A1[HID*HID];
__device__ __align__(16) uint32_t g_WBP[HID*CIN];
__device__ __align__(16) uint32_t g_WCP[COUT*HID];
__device__ float    g_u [(size_t)NROWS*HID];           // [t][b][h] fp32
__device__ uint32_t g_hs[(size_t)NROWS*HID];           // [t][b][h] packed (h0|h1)

// ---------------- helpers --------------------------------------------------
__device__ __forceinline__ void mma_bf16(float c[4], const uint32_t a[4],
                                         uint32_t b0, uint32_t b1) {
    asm volatile(
        "mma.sync.aligned.m16n8k16.row.col.f32.bf16.bf16.f32 "
        "{%0,%1,%2,%3}, {%4,%5,%6,%7}, {%8,%9}, {%0,%1,%2,%3};\n"
        : "+f"(c[0]), "+f"(c[1]), "+f"(c[2]), "+f"(c[3])
        : "r"(a[0]), "r"(a[1]), "r"(a[2]), "r"(a[3]), "r"(b0), "r"(b1));
}
__device__ __forceinline__ uint32_t pack_split(float v) {
    __nv_bfloat16 b0 = __float2bfloat16(v);
    __nv_bfloat16 b1 = __float2bfloat16(v - __bfloat162float(b0));
    return (uint32_t)__bfloat16_as_ushort(b0) | ((uint32_t)__bfloat16_as_ushort(b1) << 16);
}

// ---------------- 1) B = A^T A --------------------------------------------
__global__ void k_ata(const float* __restrict__ A) {
    __shared__ float col[HID];
    int i = blockIdx.x, j = threadIdx.x;
    col[j] = A[j*HID + i];
    __syncthreads();
    float a0=0.f,a1=0.f,a2=0.f,a3=0.f;
    #pragma unroll 16
    for (int k = 0; k < HID; k += 4) {
        a0 = fmaf(col[k+0], A[(k+0)*HID + j], a0);
        a1 = fmaf(col[k+1], A[(k+1)*HID + j], a1);
        a2 = fmaf(col[k+2], A[(k+2)*HID + j], a2);
        a3 = fmaf(col[k+3], A[(k+3)*HID + j], a3);
    }
    g_BA[i*HID + j] = (a0+a1)+(a2+a3);
}

// ---------------- 2) B <- B@B (7x => B^128) -------------------------------
__global__ void k_sq(int srcA) {
    const float* __restrict__ Bin = srcA ? g_BA : g_BB;
    float* __restrict__ Bout      = srcA ? g_BB : g_BA;
    __shared__ float row[HID];
    int i = blockIdx.x, j = threadIdx.x;
    row[j] = Bin[i*HID + j];
    __syncthreads();
    float a0=0.f,a1=0.f,a2=0.f,a3=0.f;
    #pragma unroll 16
    for (int k = 0; k < HID; k += 4) {
        a0 = fmaf(row[k+0], Bin[(k+0)*HID + j], a0);
        a1 = fmaf(row[k+1], Bin[(k+1)*HID + j], a1);
        a2 = fmaf(row[k+2], Bin[(k+2)*HID + j], a2);
        a3 = fmaf(row[k+3], Bin[(k+3)*HID + j], a3);
    }
    Bout[i*HID + j] = (a0+a1)+(a2+a3);
}

// ---------------- 3) power iteration on C = B^128 -------------------------
__device__ float red_sum(float v, float* red, int tid) {
    red[tid] = v; __syncthreads();
    for (int s = 128; s > 0; s >>= 1) { if (tid < s) red[tid] += red[tid+s]; __syncthreads(); }
    float r = red[0]; __syncthreads(); return r;
}
__device__ float red_max(float v, float* red, int tid) {
    red[tid] = v; __syncthreads();
    for (int s = 128; s > 0; s >>= 1) { if (tid < s) red[tid] = fmaxf(red[tid], red[tid+s]); __syncthreads(); }
    float r = red[0]; __syncthreads(); return r;
}
__global__ void k_power() {
    __shared__ float v[HID];
    __shared__ float red[HID];
    int tid = threadIdx.x;
    const float* __restrict__ C = g_BB;
    v[tid] = 1.0f;
    __syncthreads();
    float w = 0.f;
    for (int it = 0; it < PITERS; ++it) {
        float a0=0.f,a1=0.f,a2=0.f,a3=0.f;
        #pragma unroll 8
        for (int k = 0; k < HID; k += 4) {
            a0 = fmaf(C[(k+0)*HID + tid], v[k+0], a0);
            a1 = fmaf(C[(k+1)*HID + tid], v[k+1], a1);
            a2 = fmaf(C[(k+2)*HID + tid], v[k+2], a2);
            a3 = fmaf(C[(k+3)*HID + tid], v[k+3], a3);
        }
        w = (a0+a1)+(a2+a3);
        float m = red_max(fabsf(w), red, tid);
        v[tid] = w * (1.0f/m);
        __syncthreads();
    }
    {
        float a0=0.f,a1=0.f,a2=0.f,a3=0.f;
        #pragma unroll 8
        for (int k = 0; k < HID; k += 4) {
            a0 = fmaf(C[(k+0)*HID + tid], v[k+0], a0);
            a1 = fmaf(C[(k+1)*HID + tid], v[k+1], a1);
            a2 = fmaf(C[(k+2)*HID + tid], v[k+2], a2);
            a3 = fmaf(C[(k+3)*HID + tid], v[k+3], a3);
        }
        w = (a0+a1)+(a2+a3);
    }
    float num = red_sum(v[tid]*w,      red, tid);
    float den = red_sum(v[tid]*v[tid], red, tid);
    if (tid == 0) {
        double mu = (double)num / (double)den;       // ~ sigma^256
        double sigma = exp(log(mu) / 256.0);
        g_scale = (float)(1.0 / (sigma + 1e-5));
    }
}

// ---------------- 4a) prep A0/A1 (needs g_scale) ---------------------------
__global__ void k_prep(const float* __restrict__ A) {
    int bi = blockIdx.x, tj = threadIdx.x;       // 256 x 256
    float an = A[bi*HID + tj] * g_scale;
    __nv_bfloat16 a0 = __float2bfloat16(an);
    g_A0[bi*HID + tj] = a0;
    g_A1[bi*HID + tj] = __float2bfloat16(an - __bfloat162float(a0));
}

// ---------------- 4b) pack W_B / W_C (scale-independent) -------------------
__global__ void k_packw(const float* __restrict__ WB, const float* __restrict__ WC) {
    int bi = blockIdx.x, tj = threadIdx.x;       // 256 x 256
    if (tj < CIN)  g_WBP[bi*CIN + tj] = pack_split(WB[bi*CIN + tj]);
    if (bi < COUT) g_WCP[bi*HID + tj] = pack_split(WC[bi*HID + tj]);
}

// ---------------- 5) u = x @ W_B^T on HMMA (writes [t][b][h] fp32) --------
__global__ void __launch_bounds__(256,1) k_uprojT(const float* __restrict__ x) {
    extern __shared__ uint32_t us[];
    const int tid = threadIdx.x, w = tid >> 5, l = tid & 31, g = l >> 2, tg = l & 3;
    const int wm = w >> 1, wn = w & 1;
    const int rbase = blockIdx.x * 64;
    const int ncta  = blockIdx.y * 128;

    #pragma unroll
    for (int it = 0; it < 8; ++it) {
        int p = tid + it*256;
        int row = p >> 5, c4 = (p & 31) * 4;
        float4 v = *(const float4*)(x + (size_t)(rbase+row)*CIN + c4);
        uint4 pw = make_uint4(pack_split(v.x), pack_split(v.y), pack_split(v.z), pack_split(v.w));
        *(uint4*)(us + US_X + row*UP_PITCH + c4) = pw;
    }
    #pragma unroll
    for (int it = 0; it < 16; ++it) {
        int p = tid + it*256; int jl = p >> 5, c4 = (p & 31) * 4;
        uint4 v = *(const uint4*)(g_WBP + (size_t)(ncta+jl)*CIN + c4);
        *(uint4*)(us + US_W + jl*UP_PITCH + c4) = v;
    }
    __syncthreads();

    float acc[8][4];
    #pragma unroll
    for (int nt = 0; nt < 8; ++nt)
        #pragma unroll
        for (int q = 0; q < 4; ++q) acc[nt][q] = 0.f;

    const int mrow = wm * 16;
    #pragma unroll 2
    for (int ks = 0; ks < 8; ++ks) {
        const uint32_t* xr = us + US_X + (mrow+g)*UP_PITCH + 16*ks + 2*tg;
        uint2 a0w = *(const uint2*)xr;
        uint2 a1w = *(const uint2*)(xr + 8*UP_PITCH);
        uint2 a2w = *(const uint2*)(xr + 8);
        uint2 a3w = *(const uint2*)(xr + 8*UP_PITCH + 8);
        uint32_t x0f[4] = { __byte_perm(a0w.x,a0w.y,0x5410), __byte_perm(a1w.x,a1w.y,0x5410),
                            __byte_perm(a2w.x,a2w.y,0x5410), __byte_perm(a3w.x,a3w.y,0x5410) };
        uint32_t x1f[4] = { __byte_perm(a0w.x,a0w.y,0x7632), __byte_perm(a1w.x,a1w.y,0x7632),
                            __byte_perm(a2w.x,a2w.y,0x7632), __byte_perm(a3w.x,a3w.y,0x7632) };
        #pragma unroll
        for (int nt = 0; nt < 8; ++nt) {
            const uint32_t* wr = us + US_W + (wn*64 + nt*8 + g)*UP_PITCH + 16*ks + 2*tg;
            uint2 wA = *(const uint2*)wr;
            uint2 wB = *(const uint2*)(wr + 8);
            uint32_t w00 = __byte_perm(wA.x,wA.y,0x5410), w01 = __byte_perm(wB.x,wB.y,0x5410);
            uint32_t w10 = __byte_perm(wA.x,wA.y,0x7632), w11 = __byte_perm(wB.x,wB.y,0x7632);
            mma_bf16(acc[nt], x0f, w00, w01);
            mma_bf16(acc[nt], x1f, w00, w01);
            mma_bf16(acc[nt], x0f, w10, w11);
        }
    }
    #pragma unroll
    for (int nt = 0; nt < 8; ++nt)
        #pragma unroll
        for (int q = 0; q < 4; ++q) {
            int grow = rbase + mrow + g + ((q>>1)<<3);
            int b = grow >> 12, t = grow & 4095;
            int col = ncta + wn*64 + nt*8 + 2*tg + (q&1);
            g_u[((size_t)t*BATCH + b)*HID + col] = acc[nt][q];
        }
}

// ---------------- 6) recurrence on mma.sync bf16 ---------------------------
// 148 CTAs = 37 variable-length chunks x 4 batch-groups (NB=8).
// Light steps (first WARM-FULLWARM warm steps): skip A1 pass (2-pass).
__global__ void __launch_bounds__(256,1) k_rec() {
    extern __shared__ uint32_t sw[];
    const int tid = threadIdx.x;
    const int w = tid >> 5, l = tid & 31, g = l >> 2, tg = l & 3;
    const int wb = w * 32;
    const int chunk = blockIdx.x >> 2, bbase = (blockIdx.x & 3) * NB;

    {
        const uint32_t* A1w = (const uint32_t*)g_A1;
        for (int p = tid; p < HID*HID/2; p += 256) {
            int m = p >> 7, kp = p & 127;
            int ks = kp >> 3, c = kp & 7;
            int pos = (c < 4) ? 2*c : 2*(c-4)+1;
            sw[ks*2048 + m*8 + pos] = A1w[p];
        }
    }
    for (int p = tid; p < 2*HT_BUF; p += 256) sw[HT_OFF + p] = 0;

    uint32_t a0f[2][16][4];
    {
        const uint32_t* A0w = (const uint32_t*)g_A0;
        #pragma unroll
        for (int mt = 0; mt < 2; ++mt) {
            int mr = wb + mt*16 + g;
            #pragma unroll
            for (int ks = 0; ks < 16; ++ks) {
                int base = 8*ks + tg;
                a0f[mt][ks][0] = A0w[(size_t)mr*128 + base];
                a0f[mt][ks][1] = A0w[(size_t)(mr+8)*128 + base];
                a0f[mt][ks][2] = A0w[(size_t)mr*128 + base + 4];
                a0f[mt][ks][3] = A0w[(size_t)(mr+8)*128 + base + 4];
            }
        }
    }
    __syncthreads();

    const int t1   = (SEQ*chunk)/NCHUNK;
    const int tend = (SEQ*(chunk+1))/NCHUNK;
    int t0 = t1 - WARM; if (t0 < 0) t0 = 0;
    int lend = t1 - FULLWARM; if (lend < t0) lend = t0;

    float ur[2][4];
    {
        const float* ub = g_u + ((size_t)t0*BATCH + bbase)*HID;
        #pragma unroll
        for (int mt = 0; mt < 2; ++mt) {
            int m0 = wb + mt*16 + g;
            #pragma unroll
            for (int q = 0; q < 4; ++q)
                ur[mt][q] = ub[(size_t)(2*tg + (q&1))*HID + m0 + ((q>>1)<<3)];
        }
    }

    int par = 0;
    auto step = [&](int t, bool light) {
        const uint32_t* hb = sw + HT_OFF + par*HT_BUF;
        uint32_t* wbuf     = sw + HT_OFF + (par^1)*HT_BUF;

        float urn[2][4];
        {
            int tn = (t + 1 < tend) ? t + 1 : t;
            const float* ub = g_u + ((size_t)tn*BATCH + bbase)*HID;
            #pragma unroll
            for (int mt = 0; mt < 2; ++mt) {
                int m0 = wb + mt*16 + g;
                #pragma unroll
                for (int q = 0; q < 4; ++q)
                    urn[mt][q] = ub[(size_t)(2*tg + (q&1))*HID + m0 + ((q>>1)<<3)];
            }
        }

        float acc0[2][4] = {{0,0,0,0},{0,0,0,0}};
        float acc1[2][4] = {{0,0,0,0},{0,0,0,0}};
        float acc2[2][4] = {{0,0,0,0},{0,0,0,0}};
        if (light) {
            #pragma unroll
            for (int ks = 0; ks < 16; ++ks) {
                const uint32_t* hrow = hb + g*HT_PITCH + 16*ks + 2*tg;
                uint2 hA = *(const uint2*)hrow;
                uint2 hB = *(const uint2*)(hrow + 8);
                uint32_t b00 = __byte_perm(hA.x, hA.y, 0x5410);
                uint32_t b10 = __byte_perm(hA.x, hA.y, 0x7632);
                uint32_t b01 = __byte_perm(hB.x, hB.y, 0x5410);
                uint32_t b11 = __byte_perm(hB.x, hB.y, 0x7632);
                #pragma unroll
                for (int mt = 0; mt < 2; ++mt) {
                    mma_bf16(acc0[mt], a0f[mt][ks], b00, b01);
                    mma_bf16(acc1[mt], a0f[mt][ks], b10, b11);
                }
            }
        } else {
            #pragma unroll
            for (int ks = 0; ks < 16; ++ks) {
                const uint32_t* hrow = hb + g*HT_PITCH + 16*ks + 2*tg;
                uint2 hA = *(const uint2*)hrow;
                uint2 hB = *(const uint2*)(hrow + 8);
                uint32_t b00 = __byte_perm(hA.x, hA.y, 0x5410);
                uint32_t b10 = __byte_perm(hA.x, hA.y, 0x7632);
                uint32_t b01 = __byte_perm(hB.x, hB.y, 0x5410);
                uint32_t b11 = __byte_perm(hB.x, hB.y, 0x7632);
                const uint32_t* pan = sw + ks*2048;
                #pragma unroll
                for (int mt = 0; mt < 2; ++mt) {
                    int mr = wb + mt*16 + g;
                    uint2 rlo = *(const uint2*)(pan + mr*8 + 2*tg);
                    uint2 rhi = *(const uint2*)(pan + (mr+8)*8 + 2*tg);
                    uint32_t a1f[4] = {rlo.x, rhi.x, rlo.y, rhi.y};
                    mma_bf16(acc0[mt], a0f[mt][ks], b00, b01);
                    mma_bf16(acc1[mt], a0f[mt][ks], b10, b11);
                    mma_bf16(acc2[mt], a1f,         b00, b01);
                }
            }
        }

        {
            bool emit = (t >= t1);
            uint32_t* hsb = g_hs + ((size_t)t*BATCH + bbase)*HID;
            #pragma unroll
            for (int mt = 0; mt < 2; ++mt) {
                #pragma unroll
                for (int q = 0; q < 4; ++q) {
                    int m = wb + mt*16 + g + ((q>>1)<<3);
                    int n = 2*tg + (q&1);
                    float hv = fmaxf(acc0[mt][q] + acc1[mt][q] + acc2[mt][q] + ur[mt][q], 0.f);
                    __nv_bfloat16 h0 = __float2bfloat16(hv);
                    __nv_bfloat16 h1 = __float2bfloat16(hv - __bfloat162float(h0));
                    uint32_t word = (uint32_t)__bfloat16_as_ushort(h0)
                                  | ((uint32_t)__bfloat16_as_ushort(h1) << 16);
                    wbuf[n*HT_PITCH + m] = word;
                    if (emit) hsb[(size_t)n*HID + m] = word;
                }
            }
        }
        #pragma unroll
        for (int mt = 0; mt < 2; ++mt)
            #pragma unroll
            for (int q = 0; q < 4; ++q) ur[mt][q] = urn[mt][q];
        __syncthreads();
        par ^= 1;
    };

    for (int t = t0; t < lend; ++t) step(t, true);
    for (int t = lend; t < tend; ++t) step(t, false);
}

// ---------------- 7) y = hs @ W_C^T on HMMA (reads packed hs) -------------
__global__ void __launch_bounds__(256,1) k_yprojT(float* __restrict__ y) {
    extern __shared__ uint32_t ys[];
    const int tid = threadIdx.x, w = tid >> 5, l = tid & 31, g = l >> 2, tg = l & 3;
    const int wm = w >> 1, wn = w & 1;
    const int rbase = blockIdx.x * 64;

    #pragma unroll
    for (int it = 0; it < 16; ++it) {
        int p = tid + it*256; int row = p >> 6, c4 = (p & 63) * 4;
        uint4 v = *(const uint4*)(g_hs + (size_t)(rbase+row)*HID + c4);
        *(uint4*)(ys + YS_H + row*YP_PITCH + c4) = v;
    }
    #pragma unroll
    for (int it = 0; it < 32; ++it) {
        int p = tid + it*256; int jl = p >> 6, c4 = (p & 63) * 4;
        uint4 v = *(const uint4*)(g_WCP + (size_t)jl*HID + c4);
        *(uint4*)(ys + YS_W + jl*YP_PITCH + c4) = v;
    }
    __syncthreads();

    float acc[8][4];
    #pragma unroll
    for (int nt = 0; nt < 8; ++nt)
        #pragma unroll
        for (int q = 0; q < 4; ++q) acc[nt][q] = 0.f;

    const int mrow = wm * 16;
    #pragma unroll 2
    for (int ks = 0; ks < 16; ++ks) {
        const uint32_t* hr = ys + YS_H + (mrow+g)*YP_PITCH + 16*ks + 2*tg;
        uint2 a0w = *(const uint2*)hr;
        uint2 a1w = *(const uint2*)(hr + 8*YP_PITCH);
        uint2 a2w = *(const uint2*)(hr + 8);
        uint2 a3w = *(const uint2*)(hr + 8*YP_PITCH + 8);
        uint32_t h0f[4] = { __byte_perm(a0w.x,a0w.y,0x5410), __byte_perm(a1w.x,a1w.y,0x5410),
                            __byte_perm(a2w.x,a2w.y,0x5410), __byte_perm(a3w.x,a3w.y,0x5410) };
        uint32_t h1f[4] = { __byte_perm(a0w.x,a0w.y,0x7632), __byte_perm(a1w.x,a1w.y,0x7632),
                            __byte_perm(a2w.x,a2w.y,0x7632), __byte_perm(a3w.x,a3w.y,0x7632) };
        #pragma unroll
        for (int nt = 0; nt < 8; ++nt) {
            const uint32_t* wr = ys + YS_W + (wn*64 + nt*8 + g)*YP_PITCH + 16*ks + 2*tg;
            uint2 wA = *(const uint2*)wr;
            uint2 wB = *(const uint2*)(wr + 8);
            uint32_t w00 = __byte_perm(wA.x,wA.y,0x5410), w01 = __byte_perm(wB.x,wB.y,0x5410);
            uint32_t w10 = __byte_perm(wA.x,wA.y,0x7632), w11 = __byte_perm(wB.x,wB.y,0x7632);
            mma_bf16(acc[nt], h0f, w00, w01);
            mma_bf16(acc[nt], h1f, w00, w01);
            mma_bf16(acc[nt], h0f, w10, w11);
        }
    }
    #pragma unroll
    for (int nt = 0; nt < 8; ++nt)
        #pragma unroll
        for (int q = 0; q < 4; ++q) {
            int grow = rbase + mrow + g + ((q>>1)<<3);   // row = t*32 + b
            int t = grow >> 5, b = grow & 31;
            int col = wn*64 + nt*8 + 2*tg + (q&1);
            y[((size_t)b*SEQ + t)*COUT + col] = acc[nt][q];
        }
}

// ---------------- launch ---------------------------------------------------
extern "C" void kernel_launch(void* const* d_in, const int* in_sizes, int n_in,
                              void* d_out, int out_size) {
    const float* x  = (const float*)d_in[0];
    const float* A  = (const float*)d_in[1];
    const float* WB = (const float*)d_in[2];
    const float* WC = (const float*)d_in[3];
    float* y = (float*)d_out;

    static cudaStream_t s2 = nullptr;
    static cudaEvent_t eF = nullptr, eJ = nullptr;
    if (s2 == nullptr) {
        cudaStreamCreateWithFlags(&s2, cudaStreamNonBlocking);
        cudaEventCreateWithFlags(&eF, cudaEventDisableTiming);
        cudaEventCreateWithFlags(&eJ, cudaEventDisableTiming);
        cudaFuncSetAttribute(k_rec,    cudaFuncAttributeMaxDynamicSharedMemorySize, REC_SMEM);
        cudaFuncSetAttribute(k_uprojT, cudaFuncAttributeMaxDynamicSharedMemorySize, UP_SMEM);
        cudaFuncSetAttribute(k_yprojT, cudaFuncAttributeMaxDynamicSharedMemorySize, YP_SMEM);
    }

    // fork: u-projection branch (independent of spectral norm)
    cudaEventRecord(eF, 0);
    cudaStreamWaitEvent(s2, eF, 0);
    k_packw<<<HID, HID, 0, s2>>>(WB, WC);
    k_uprojT<<<dim3(NROWS/64, 2), 256, UP_SMEM, s2>>>(x);
    cudaEventRecord(eJ, s2);

    // spectral-norm branch on the main stream
    k_ata<<<HID, HID>>>(A);
    k_sq<<<HID, HID>>>(1);
    k_sq<<<HID, HID>>>(0);
    k_sq<<<HID, HID>>>(1);
    k_sq<<<HID, HID>>>(0);
    k_sq<<<HID, HID>>>(1);
    k_sq<<<HID, HID>>>(0);
    k_sq<<<HID, HID>>>(1);            // C = B^128 in g_BB
    k_power<<<1, HID>>>();
    k_prep<<<HID, HID>>>(A);

    // join, then recurrence + output projection
    cudaStreamWaitEvent(0, eJ, 0);
    k_rec<<<NCHUNK*(BATCH/NB), 256, REC_SMEM>>>();
    k_yprojT<<<NROWS/64, 256, YP_SMEM>>>(y);
}